// round 9
// baseline (speedup 1.0000x reference)
#include <cuda_runtime.h>
#include <cuda_bf16.h>
#include <cstdint>

typedef __nv_bfloat16 bf16;

#define BATCH 4
#define SEQ   4096
#define CH    1024
#define NHEAD 16
#define DH    64
#define MROWS (BATCH*SEQ)     /* 16384 */
#define KDIM  CH              /* 1024  */
#define NQKV  (3*CH)          /* 3072  */
#define NSPLIT 16
#define BHCNT (BATCH*NHEAD)   /* 64    */

// int8 GEMM tiling
#define BM 128
#define BN 128
#define BK8 64                  /* int8 K bytes per stage chunk (2 k32 MMA steps) */
#define NT8 (KDIM/BK8)          /* 16 */
#define STAGES 4
#define NTHREADS 512
#define LDS8 80                 /* smem row stride bytes (64 data + 16 pad) */
#define ARR8 (128*LDS8)         /* 10240 per array (ah/al/bh/bl) */
#define STG8 (4*ARR8)           /* 40960 per stage */
#define SMEM8 (STAGES*STG8)     /* 163840 */

#define RQ 254.0f               /* residual quant scale */

// ------------------------- scratch (device globals; no allocs) -------------------------
__device__ int8_t g_a8x[(size_t)MROWS*2048];      // [ah | al] per row
__device__ int8_t g_a8attn[(size_t)MROWS*2048];
__device__ int8_t g_b8qkv[(size_t)NQKV*2048];
__device__ int8_t g_b8out[(size_t)CH*2048];
__device__ float  g_sx[MROWS];
__device__ float  g_sattn[MROWS];
__device__ float  g_sqkv[NQKV];
__device__ float  g_sout[CH];
__device__ float  g_qkv[(size_t)MROWS*NQKV];
__device__ float  g_attn[(size_t)MROWS*CH];
__device__ float  g_kv_part[(size_t)NSPLIT*BHCNT*DH*DH];
__device__ float  g_ksum_part[(size_t)NSPLIT*BHCNT*DH];
__device__ float  g_kv[(size_t)BHCNT*DH*DH];
__device__ float  g_denom[(size_t)BHCNT*SEQ];

// ------------------------- helpers -------------------------
__device__ __forceinline__ uint32_t smem_u32(const void* p) {
    uint32_t a;
    asm("{ .reg .u64 t; cvta.to.shared.u64 t, %1; cvt.u32.u64 %0, t; }" : "=r"(a) : "l"(p));
    return a;
}
__device__ __forceinline__ void cp_async16(uint32_t s, const void* g) {
    asm volatile("cp.async.cg.shared.global [%0], [%1], 16;" :: "r"(s), "l"(g) : "memory");
}
__device__ __forceinline__ void cp_commit() {
    asm volatile("cp.async.commit_group;" ::: "memory");
}
template<int N>
__device__ __forceinline__ void cp_wait() {
    asm volatile("cp.async.wait_group %0;" :: "n"(N) : "memory");
}
__device__ __forceinline__ void ldm_x4(uint32_t* r, uint32_t addr) {
    asm volatile("ldmatrix.sync.aligned.m8n8.x4.shared.b16 {%0,%1,%2,%3}, [%4];"
                 : "=r"(r[0]), "=r"(r[1]), "=r"(r[2]), "=r"(r[3]) : "r"(addr));
}
__device__ __forceinline__ void imma(int* d, const uint32_t* a, uint32_t b0, uint32_t b1) {
    asm volatile("mma.sync.aligned.m16n8k32.row.col.s32.s8.s8.s32 "
                 "{%0,%1,%2,%3}, {%4,%5,%6,%7}, {%8,%9}, {%0,%1,%2,%3};"
                 : "+r"(d[0]), "+r"(d[1]), "+r"(d[2]), "+r"(d[3])
                 : "r"(a[0]), "r"(a[1]), "r"(a[2]), "r"(a[3]), "r"(b0), "r"(b1));
}
__device__ __forceinline__ float featf(float x) {
    const float s = 0.35355339059327373f;       // 64^-0.25
    return (x > 0.0f) ? (x + 1.0f) * s : __expf(x) * s;
}

// ------------------------- per-row residual int8 quantization -------------------------
// dst row layout: [ah(1024) | al(1024)], a = scale * (ah + al/254)
__global__ void __launch_bounds__(256) quant_kernel(const float* __restrict__ src,
                                                    int8_t* __restrict__ dst,
                                                    float* __restrict__ scale) {
    const int row = blockIdx.x;
    const int tid = threadIdx.x;
    __shared__ float red[8];
    __shared__ float s_inv;

    const float4 v = *(const float4*)&src[(size_t)row * 1024 + tid * 4];
    float m = fmaxf(fmaxf(fabsf(v.x), fabsf(v.y)), fmaxf(fabsf(v.z), fabsf(v.w)));
    #pragma unroll
    for (int o = 16; o > 0; o >>= 1) m = fmaxf(m, __shfl_xor_sync(0xFFFFFFFFu, m, o));
    if ((tid & 31) == 0) red[tid >> 5] = m;
    __syncthreads();
    if (tid == 0) {
        float mm = red[0];
        #pragma unroll
        for (int i = 1; i < 8; ++i) mm = fmaxf(mm, red[i]);
        scale[row] = (mm > 0.0f) ? mm / 127.0f : 1.0f;
        s_inv = (mm > 0.0f) ? 127.0f / mm : 0.0f;
    }
    __syncthreads();
    const float inv = s_inv;
    float t[4] = {v.x * inv, v.y * inv, v.z * inv, v.w * inv};
    char hb[4], lb[4];
    #pragma unroll
    for (int i = 0; i < 4; ++i) {
        const float h = rintf(t[i]);
        hb[i] = (char)(int)h;
        lb[i] = (char)(int)rintf((t[i] - h) * RQ);
    }
    *(char4*)&dst[(size_t)row * 2048 + tid * 4]        = make_char4(hb[0], hb[1], hb[2], hb[3]);
    *(char4*)&dst[(size_t)row * 2048 + 1024 + tid * 4] = make_char4(lb[0], lb[1], lb[2], lb[3]);
}

// ------------------------- int8x3 GEMM: C[m,n] = sum_k A[m,k]*B[n,k] -------------------------
// MODE 0: x @ wqkv^T -> g_qkv (feat on q,k cols). MODE 1: attn @ wout^T + bias -> Cout.
template<int MODE>
__global__ void __launch_bounds__(NTHREADS) gemm_s8(float* __restrict__ CoutExt,
                                                    const float* __restrict__ bias) {
    constexpr int NC = (MODE == 0) ? NQKV : CH;
    const int8_t* __restrict__ A8 = (MODE == 0) ? g_a8x   : g_a8attn;
    const int8_t* __restrict__ B8 = (MODE == 0) ? g_b8qkv : g_b8out;
    const float*  __restrict__ sA = (MODE == 0) ? g_sx    : g_sattn;
    const float*  __restrict__ sB = (MODE == 0) ? g_sqkv  : g_sout;
    float* __restrict__ Cp = (MODE == 0) ? g_qkv : CoutExt;

    extern __shared__ __align__(16) char smem_raw[];
    const uint32_t sb = smem_u32(smem_raw);

    const int tid  = threadIdx.x;
    const int wid  = tid >> 5;
    const int lane = tid & 31;
    const int wm_ = wid >> 2;    // 0..3 (M dir, 32 rows)
    const int wn_ = wid & 3;     // 0..3 (N dir, 32 cols)
    const int m0 = blockIdx.y * BM;
    const int n0 = blockIdx.x * BN;

    // cp.async slots: per stage 4 arrays x 128 rows x 4 16B-chunks = 2048; 4 per thread.
    // j = array id: 0=ah, 1=al, 2=bh, 3=bl
    const char* gptr[4];
    uint32_t    sptr[4];
    {
        const int r = tid >> 2, c16 = tid & 3;
        #pragma unroll
        for (int j = 0; j < 4; ++j) {
            const int8_t* base = (j < 2) ? A8 : B8;
            const int row = ((j < 2) ? m0 : n0) + r;
            gptr[j] = (const char*)(base + (size_t)row * 2048 + (j & 1) * 1024 + c16 * 16);
            sptr[j] = sb + j * ARR8 + r * LDS8 + c16 * 16;
        }
    }

    int acc1[2][4][4], acc2[2][4][4];
    #pragma unroll
    for (int i = 0; i < 2; i++)
        #pragma unroll
        for (int j = 0; j < 4; j++)
            #pragma unroll
            for (int e = 0; e < 4; e++) { acc1[i][j][e] = 0; acc2[i][j][e] = 0; }

    // prologue
    #pragma unroll
    for (int s = 0; s < STAGES - 1; ++s) {
        const uint32_t so = (uint32_t)s * STG8;
        #pragma unroll
        for (int j = 0; j < 4; ++j) cp_async16(sptr[j] + so, gptr[j] + (size_t)s * BK8);
        cp_commit();
    }

    // ldmatrix per-lane address components
    const int lrowA = lane & 15;                 // A: row within 16
    const int hiA   = (lane >> 4) << 4;          // A: +16B for k-hi half
    const int nrB   = (lane & 7) + ((lane >> 4) << 3);   // B: n-row within 16
    const int boffB = ((lane >> 3) & 1) << 4;            // B: +16B for k-hi half

    for (int kt = 0; kt < NT8; ++kt) {
        cp_wait<STAGES - 2>();
        __syncthreads();

        const int ns = kt + STAGES - 1;
        if (ns < NT8) {
            const uint32_t so = (uint32_t)(ns & (STAGES - 1)) * STG8;
            #pragma unroll
            for (int j = 0; j < 4; ++j) cp_async16(sptr[j] + so, gptr[j] + (size_t)ns * BK8);
        }
        cp_commit();

        const uint32_t stq = sb + (uint32_t)(kt & (STAGES - 1)) * STG8;
        const uint32_t aAh = stq + wm_ * 32 * LDS8;
        const uint32_t aAl = aAh + ARR8;
        const uint32_t aBh = stq + 2 * ARR8 + wn_ * 32 * LDS8;
        const uint32_t aBl = aBh + ARR8;

        #pragma unroll
        for (int s = 0; s < 2; ++s) {       // two k32 steps per 64B chunk
            uint32_t ah[2][4], al[2][4];
            uint32_t bh[2][4], bl[2][4];    // [pair j2][t0.b0,t0.b1,t1.b0,t1.b1]
            #pragma unroll
            for (int i = 0; i < 2; ++i) {
                const uint32_t ro = (i * 16 + lrowA) * LDS8 + s * 32 + hiA;
                ldm_x4(ah[i], aAh + ro);
                ldm_x4(al[i], aAl + ro);
            }
            #pragma unroll
            for (int j2 = 0; j2 < 2; ++j2) {
                const uint32_t ro = (j2 * 16 + nrB) * LDS8 + s * 32 + boffB;
                ldm_x4(bh[j2], aBh + ro);
                ldm_x4(bl[j2], aBl + ro);
            }
            // term-major: acc1 += ah*bh ; acc2 += ah*bl ; acc2 += al*bh
            #pragma unroll
            for (int i = 0; i < 2; ++i)
                #pragma unroll
                for (int j = 0; j < 4; ++j)
                    imma(acc1[i][j], ah[i], bh[j >> 1][(j & 1) * 2], bh[j >> 1][(j & 1) * 2 + 1]);
            #pragma unroll
            for (int i = 0; i < 2; ++i)
                #pragma unroll
                for (int j = 0; j < 4; ++j)
                    imma(acc2[i][j], ah[i], bl[j >> 1][(j & 1) * 2], bl[j >> 1][(j & 1) * 2 + 1]);
            #pragma unroll
            for (int i = 0; i < 2; ++i)
                #pragma unroll
                for (int j = 0; j < 4; ++j)
                    imma(acc2[i][j], al[i], bh[j >> 1][(j & 1) * 2], bh[j >> 1][(j & 1) * 2 + 1]);
        }
        __syncthreads();
    }
    cp_wait<0>();
    __syncthreads();

    // stage combined (acc1 + acc2/254) floats into smem, then dequant+fuse+store
    float* Cs = (float*)smem_raw;   // 128 x 132 floats = 67584 B
    {
        const int rb = wm_ * 32 + (lane >> 2);
        const int cb = wn_ * 32 + 2 * (lane & 3);
        #pragma unroll
        for (int i = 0; i < 2; ++i)
            #pragma unroll
            for (int j = 0; j < 4; ++j) {
                const int r0 = rb + i * 16, c0 = cb + j * 8;
                const float v0 = (float)acc1[i][j][0] + (float)acc2[i][j][0] * (1.0f / RQ);
                const float v1 = (float)acc1[i][j][1] + (float)acc2[i][j][1] * (1.0f / RQ);
                const float v2 = (float)acc1[i][j][2] + (float)acc2[i][j][2] * (1.0f / RQ);
                const float v3 = (float)acc1[i][j][3] + (float)acc2[i][j][3] * (1.0f / RQ);
                *(float2*)&Cs[r0 * 132 + c0]       = make_float2(v0, v1);
                *(float2*)&Cs[(r0 + 8) * 132 + c0] = make_float2(v2, v3);
            }
    }
    __syncthreads();
    for (int i = tid; i < BM * BN / 4; i += NTHREADS) {
        const int row = i >> 5;
        const int c4  = (i & 31) << 2;
        const int gn  = n0 + c4;
        float4 v = *(const float4*)&Cs[row * 132 + c4];
        const float sa = sA[m0 + row];
        const float4 sb4 = *(const float4*)&sB[gn];
        v.x *= sa * sb4.x; v.y *= sa * sb4.y; v.z *= sa * sb4.z; v.w *= sa * sb4.w;
        if (MODE == 0) {
            if (gn < 2 * CH) {
                v.x = featf(v.x); v.y = featf(v.y); v.z = featf(v.z); v.w = featf(v.w);
            }
        } else {
            v.x += bias[gn]; v.y += bias[gn + 1]; v.z += bias[gn + 2]; v.w += bias[gn + 3];
        }
        *(float4*)&Cp[(size_t)(m0 + row) * NC + gn] = v;
    }
}

// ------------------------- kv = k^T v partials + ksum partials -------------------------
__global__ void __launch_bounds__(256) kv_partial_kernel() {
    const int s  = blockIdx.x;
    const int bh = blockIdx.y;
    const int b = bh >> 4, h = bh & 15;
    const int tid = threadIdx.x;
    const int d  = tid >> 2;
    const int e0 = (tid & 3) << 4;

    __shared__ __align__(16) float ks_[8][64];
    __shared__ __align__(16) float vs_[8][64];

    float acc[16];
    #pragma unroll
    for (int i = 0; i < 16; i++) acc[i] = 0.0f;
    float ksum = 0.0f;

    const float* kbase = g_qkv + (size_t)(b*SEQ)*NQKV + CH + h*DH;
    const float* vbase = kbase + CH;
    int nbase = s * (SEQ / NSPLIT);
    for (int it = 0; it < 32; ++it, nbase += 8) {
        #pragma unroll
        for (int j = 0; j < 2; ++j) {
            const int idx = tid + j*256;
            const int r = idx >> 6, c = idx & 63;
            ks_[r][c] = kbase[(size_t)(nbase + r)*NQKV + c];
            vs_[r][c] = vbase[(size_t)(nbase + r)*NQKV + c];
        }
        __syncthreads();
        #pragma unroll
        for (int r = 0; r < 8; ++r) {
            const float kd = ks_[r][d];
            ksum += kd;
            #pragma unroll
            for (int j4 = 0; j4 < 4; ++j4) {
                const float4 vv = *(const float4*)&vs_[r][e0 + j4*4];
                acc[j4*4+0] += kd*vv.x; acc[j4*4+1] += kd*vv.y;
                acc[j4*4+2] += kd*vv.z; acc[j4*4+3] += kd*vv.w;
            }
        }
        __syncthreads();
    }
    float* outp = g_kv_part + ((size_t)s*BHCNT + bh)*(DH*DH) + d*DH + e0;
    #pragma unroll
    for (int j4 = 0; j4 < 4; ++j4)
        *(float4*)&outp[j4*4] = make_float4(acc[j4*4], acc[j4*4+1], acc[j4*4+2], acc[j4*4+3]);
    if ((tid & 3) == 0)
        g_ksum_part[((size_t)s*BHCNT + bh)*DH + d] = ksum;
}

__global__ void kv_reduce_kernel() {
    const int i = blockIdx.x * 256 + threadIdx.x;
    float s = 0.0f;
    #pragma unroll
    for (int p = 0; p < NSPLIT; ++p) s += g_kv_part[(size_t)p*(BHCNT*DH*DH) + i];
    g_kv[i] = s;
}

// ------------------------- ksum reduce + denom^-1 -------------------------
__global__ void __launch_bounds__(256) denom_kernel() {
    const int bh = blockIdx.y;
    const int b = bh >> 4, h = bh & 15;
    const int tid = threadIdx.x;
    __shared__ float ksum_s[64];
    if (tid < 64) {
        float s = 0.0f;
        #pragma unroll
        for (int p = 0; p < NSPLIT; ++p) s += g_ksum_part[((size_t)p*BHCNT + bh)*DH + tid];
        ksum_s[tid] = s;
    }
    __syncthreads();
    const int n = blockIdx.x * 256 + tid;
    const float* qp = g_qkv + (size_t)(b*SEQ + n)*NQKV + h*DH;
    float a = 0.0f;
    #pragma unroll
    for (int d4 = 0; d4 < DH; d4 += 4) {
        const float4 q4 = *(const float4*)&qp[d4];
        a += q4.x*ksum_s[d4] + q4.y*ksum_s[d4+1] + q4.z*ksum_s[d4+2] + q4.w*ksum_s[d4+3];
    }
    g_denom[(size_t)bh*SEQ + n] = 1.0f / (a + 1e-6f);
}

// ------------------------- out = (q @ kv) * denom^-1 -> g_attn fp32 -------------------------
__global__ void __launch_bounds__(256) attn_kernel() {
    const int bh = blockIdx.y;
    const int chunk = blockIdx.x;
    const int b = bh >> 4, h = bh & 15;
    const int tid = threadIdx.x;
    const int base = chunk * 64;

    __shared__ __align__(16) float kv_s[64*64];
    __shared__ float q_s[64*65];
    __shared__ float inv_s[64];

    for (int i = tid; i < DH*DH; i += 256) kv_s[i] = g_kv[(size_t)bh*(DH*DH) + i];
    for (int i = tid; i < 64*64; i += 256) {
        const int r = i >> 6, d = i & 63;
        q_s[r*65 + d] = g_qkv[(size_t)(b*SEQ + base + r)*NQKV + h*DH + d];
    }
    if (tid < 64) inv_s[tid] = g_denom[(size_t)bh*SEQ + base + tid];
    __syncthreads();

    const int rsub = tid >> 4;
    const int e4   = (tid & 15) << 2;
    #pragma unroll
    for (int p = 0; p < 4; ++p) {
        const int row = p*16 + rsub;
        float4 acc = make_float4(0.f, 0.f, 0.f, 0.f);
        #pragma unroll 8
        for (int d = 0; d < DH; ++d) {
            const float qv = q_s[row*65 + d];
            const float4 kvv = *(const float4*)&kv_s[d*DH + e4];
            acc.x += qv*kvv.x; acc.y += qv*kvv.y; acc.z += qv*kvv.z; acc.w += qv*kvv.w;
        }
        const float inv = inv_s[row];
        acc.x *= inv; acc.y *= inv; acc.z *= inv; acc.w *= inv;
        *(float4*)&g_attn[(size_t)(b*SEQ + base + row)*CH + h*DH + e4] = acc;
    }
}

// ------------------------- launch -------------------------
extern "C" void kernel_launch(void* const* d_in, const int* in_sizes, int n_in,
                              void* d_out, int out_size) {
    (void)in_sizes; (void)n_in; (void)out_size;
    const float* x     = (const float*)d_in[0];
    const float* w_qkv = (const float*)d_in[1];
    const float* w_out = (const float*)d_in[2];
    const float* b_out = (const float*)d_in[3];
    float* out = (float*)d_out;

    // resolve device-global addresses host-side
    int8_t *a8x, *a8attn, *b8qkv, *b8out;
    float *sx, *sattn, *sqkv, *sout, *attn;
    cudaGetSymbolAddress((void**)&a8x,   g_a8x);
    cudaGetSymbolAddress((void**)&a8attn,g_a8attn);
    cudaGetSymbolAddress((void**)&b8qkv, g_b8qkv);
    cudaGetSymbolAddress((void**)&b8out, g_b8out);
    cudaGetSymbolAddress((void**)&sx,    g_sx);
    cudaGetSymbolAddress((void**)&sattn, g_sattn);
    cudaGetSymbolAddress((void**)&sqkv,  g_sqkv);
    cudaGetSymbolAddress((void**)&sout,  g_sout);
    cudaGetSymbolAddress((void**)&attn,  g_attn);

    quant_kernel<<<MROWS, 256>>>(x,     a8x,   sx);
    quant_kernel<<<NQKV,  256>>>(w_qkv, b8qkv, sqkv);
    quant_kernel<<<CH,    256>>>(w_out, b8out, sout);

    cudaFuncSetAttribute(gemm_s8<0>, cudaFuncAttributeMaxDynamicSharedMemorySize, (int)SMEM8);
    gemm_s8<0><<<dim3(NQKV/BN, MROWS/BM), NTHREADS, SMEM8>>>(nullptr, nullptr);

    kv_partial_kernel<<<dim3(NSPLIT, BHCNT), 256>>>();
    kv_reduce_kernel<<<(BHCNT*DH*DH)/256, 256>>>();
    denom_kernel<<<dim3(SEQ/256, BHCNT), 256>>>();
    attn_kernel<<<dim3(SEQ/64, BHCNT), 256>>>();

    quant_kernel<<<MROWS, 256>>>(attn, a8attn, sattn);

    cudaFuncSetAttribute(gemm_s8<1>, cudaFuncAttributeMaxDynamicSharedMemorySize, (int)SMEM8);
    gemm_s8<1><<<dim3(CH/BN, MROWS/BM), NTHREADS, SMEM8>>>(out, b_out);
}

// round 10
// speedup vs baseline: 1.9059x; 1.9059x over previous
#include <cuda_runtime.h>
#include <cuda_fp16.h>
#include <mma.h>
#include <cstdint>

using namespace nvcuda;

#define BATCH 4
#define SEQ   4096
#define CH    1024
#define NHEAD 16
#define DH    64
#define MROWS (BATCH*SEQ)     /* 16384 */
#define KDIM  CH              /* 1024  */
#define NQKV  (3*CH)          /* 3072  */
#define NSPLIT 16
#define BHCNT (BATCH*NHEAD)   /* 64    */

// GEMM tiling
#define BM 128
#define BN 128
#define BK 32
#define NT (KDIM/BK)            /* 32 K-tiles */
#define STAGES 4
#define LDA 40                  /* half elems; 80 B row stride (16B-aligned) */
#define ARR_BYTES (128*LDA*2)   /* 10240 B per array (Ah/Al/Bh/Bl)          */
#define STAGE_BYTES (4*ARR_BYTES)          /* 40960  */
#define GEMM_SMEM (STAGES*STAGE_BYTES)     /* 163840 */

// ------------------------- scratch (device globals; no allocs) -------------------------
__device__ __half g_x_hi[(size_t)MROWS*KDIM];
__device__ __half g_x_lo[(size_t)MROWS*KDIM];
__device__ __half g_wqkv_hi[(size_t)NQKV*KDIM];
__device__ __half g_wqkv_lo[(size_t)NQKV*KDIM];
__device__ __half g_wout_hi[(size_t)CH*KDIM];
__device__ __half g_wout_lo[(size_t)CH*KDIM];
__device__ float  g_qkv[(size_t)MROWS*NQKV];
__device__ float  g_kv_part[(size_t)NSPLIT*BHCNT*DH*DH];
__device__ float  g_ksum_part[(size_t)NSPLIT*BHCNT*DH];
__device__ float  g_kv[(size_t)BHCNT*DH*DH];
__device__ float  g_denom[(size_t)BHCNT*SEQ];
__device__ __half g_attn_hi[(size_t)MROWS*CH];
__device__ __half g_attn_lo[(size_t)MROWS*CH];

// ------------------------- helpers -------------------------
__device__ __forceinline__ uint32_t smem_u32(const void* p) {
    uint32_t a;
    asm("{ .reg .u64 t; cvta.to.shared.u64 t, %1; cvt.u32.u64 %0, t; }" : "=r"(a) : "l"(p));
    return a;
}
__device__ __forceinline__ void cp_async16(uint32_t s, const void* g) {
    asm volatile("cp.async.cg.shared.global [%0], [%1], 16;" :: "r"(s), "l"(g) : "memory");
}
__device__ __forceinline__ void cp_commit() {
    asm volatile("cp.async.commit_group;" ::: "memory");
}
template<int N>
__device__ __forceinline__ void cp_wait() {
    asm volatile("cp.async.wait_group %0;" :: "n"(N) : "memory");
}
__device__ __forceinline__ float featf(float x) {
    const float s = 0.35355339059327373f;       // 64^-0.25
    return (x > 0.0f) ? (x + 1.0f) * s : __expf(x) * s;
}

// ------------------------- split fp32 -> fp16 hi/lo -------------------------
__global__ void split_kernel(const float* __restrict__ src, int n, int mode) {
    __half *hi, *lo;
    if (mode == 0)      { hi = g_x_hi;    lo = g_x_lo; }
    else if (mode == 1) { hi = g_wqkv_hi; lo = g_wqkv_lo; }
    else                { hi = g_wout_hi; lo = g_wout_lo; }
    int i = blockIdx.x * blockDim.x + threadIdx.x;
    int stride = gridDim.x * blockDim.x;
    for (; i < n; i += stride) {
        float v = src[i];
        __half h = __float2half(v);
        float r = v - __half2float(h);
        hi[i] = h;
        lo[i] = __float2half(r);
    }
}

// ------------------------- fp16x3 GEMM, mixed accumulators, 4-stage cp.async -------------------------
// C[m,n] = sum_k A[m,k]*B[n,k]
// hh term -> f32 accum ; hl + lh terms -> f16 accum (terms are ~2^-11 relative; f16 acc safe)
// MODE 0: x @ wqkv^T, feat epilogue on q,k cols -> g_qkv.  MODE 1: attn @ wout^T + bias -> Cout.
template<int MODE>
__global__ void __launch_bounds__(256) gemm_f16x3(float* __restrict__ CoutExt,
                                                  const float* __restrict__ bias) {
    constexpr int NC = (MODE == 0) ? NQKV : CH;
    const __half* __restrict__ Ahi = (MODE == 0) ? g_x_hi    : g_attn_hi;
    const __half* __restrict__ Alo = (MODE == 0) ? g_x_lo    : g_attn_lo;
    const __half* __restrict__ Bhi = (MODE == 0) ? g_wqkv_hi : g_wout_hi;
    const __half* __restrict__ Blo = (MODE == 0) ? g_wqkv_lo : g_wout_lo;
    float* __restrict__ Cp = (MODE == 0) ? g_qkv : CoutExt;

    extern __shared__ __align__(16) char smem_raw[];
    const uint32_t sb = smem_u32(smem_raw);

    const int tid = threadIdx.x;
    const int wid = tid >> 5;
    const int wm_ = wid >> 1;    // 0..3 (M dir, 32 rows each)
    const int wn_ = wid & 1;     // 0..1 (N dir, 64 cols each)
    const int m0 = blockIdx.y * BM;
    const int n0 = blockIdx.x * BN;

    // Per-thread cp.async slots: 2048 16B-chunks per stage, 8 per thread.
    const char* gptr[8];
    uint32_t    sptr[8];
    #pragma unroll
    for (int j = 0; j < 8; ++j) {
        const int idx = tid + j * 256;
        const int arr = idx >> 9, r = (idx >> 2) & 127, c16 = idx & 3;
        const __half* base = (arr == 0) ? Ahi : (arr == 1) ? Alo : (arr == 2) ? Bhi : Blo;
        const int row = ((arr < 2) ? m0 : n0) + r;
        gptr[j] = (const char*)(base + (size_t)row * KDIM + c16 * 8);
        sptr[j] = sb + arr * ARR_BYTES + r * (LDA * 2) + c16 * 16;
    }

    wmma::fragment<wmma::accumulator,16,16,16,float>  accF[2][4];
    wmma::fragment<wmma::accumulator,16,16,16,__half> accH[2][4];
    #pragma unroll
    for (int i = 0; i < 2; i++)
        #pragma unroll
        for (int j = 0; j < 4; j++) {
            wmma::fill_fragment(accF[i][j], 0.0f);
            wmma::fill_fragment(accH[i][j], __float2half(0.0f));
        }

    // prologue: stages 0..STAGES-2
    #pragma unroll
    for (int s = 0; s < STAGES - 1; ++s) {
        const uint32_t so = (uint32_t)(s & (STAGES-1)) * STAGE_BYTES;
        #pragma unroll
        for (int j = 0; j < 8; ++j) cp_async16(sptr[j] + so, gptr[j] + (size_t)s * (BK*2));
        cp_commit();
    }

    for (int kt = 0; kt < NT; ++kt) {
        cp_wait<STAGES - 2>();
        __syncthreads();

        const int ns = kt + STAGES - 1;
        if (ns < NT) {
            const uint32_t so = (uint32_t)(ns & (STAGES-1)) * STAGE_BYTES;
            #pragma unroll
            for (int j = 0; j < 8; ++j) cp_async16(sptr[j] + so, gptr[j] + (size_t)ns * (BK*2));
        }
        cp_commit();

        const __half* sA_h = (const __half*)(smem_raw + (size_t)(kt & (STAGES-1)) * STAGE_BYTES);
        const __half* sA_l = sA_h + 128*LDA;
        const __half* sB_h = sA_l + 128*LDA;
        const __half* sB_l = sB_h + 128*LDA;
        const __half* pAh = sA_h + wm_*32*LDA;
        const __half* pAl = sA_l + wm_*32*LDA;
        const __half* pBh = sB_h + wn_*64*LDA;
        const __half* pBl = sB_l + wn_*64*LDA;

        #pragma unroll
        for (int ks = 0; ks < BK; ks += 16) {
            wmma::fragment<wmma::matrix_a,16,16,16,__half,wmma::row_major> ah[2], al[2];
            #pragma unroll
            for (int i = 0; i < 2; i++) {
                wmma::load_matrix_sync(ah[i], pAh + i*16*LDA + ks, LDA);
                wmma::load_matrix_sync(al[i], pAl + i*16*LDA + ks, LDA);
            }
            #pragma unroll
            for (int j = 0; j < 4; j++) {
                wmma::fragment<wmma::matrix_b,16,16,16,__half,wmma::col_major> bh, bl;
                wmma::load_matrix_sync(bh, pBh + j*16*LDA + ks, LDA);
                wmma::load_matrix_sync(bl, pBl + j*16*LDA + ks, LDA);
                // hh term: fp32 accumulate
                wmma::mma_sync(accF[0][j], ah[0], bh, accF[0][j]);
                wmma::mma_sync(accF[1][j], ah[1], bh, accF[1][j]);
                // hl + lh terms: fp16 accumulate
                wmma::mma_sync(accH[0][j], ah[0], bl, accH[0][j]);
                wmma::mma_sync(accH[1][j], ah[1], bl, accH[1][j]);
                wmma::mma_sync(accH[0][j], al[0], bh, accH[0][j]);
                wmma::mma_sync(accH[1][j], al[1], bh, accH[1][j]);
            }
        }
        __syncthreads();
    }
    cp_wait<0>();
    __syncthreads();

    // epilogue: stage f32 + f16 accumulators into smem, merge on global store
    float*  Cs  = (float*)smem_raw;                  // 128 x 132 f32 = 67584 B
    __half* Chs = (__half*)(smem_raw + 67584);       // 128 x 132 f16 = 33792 B
    #pragma unroll
    for (int i = 0; i < 2; i++)
        #pragma unroll
        for (int j = 0; j < 4; j++) {
            wmma::store_matrix_sync(Cs  + (wm_*32 + i*16)*132 + wn_*64 + j*16,
                                    accF[i][j], 132, wmma::mem_row_major);
            wmma::store_matrix_sync(Chs + (wm_*32 + i*16)*132 + wn_*64 + j*16,
                                    accH[i][j], 132, wmma::mem_row_major);
        }
    __syncthreads();
    for (int i = tid; i < BM*BN/4; i += 256) {
        const int row = i >> 5;
        const int c4  = (i & 31) << 2;
        float4 v = *(const float4*)&Cs[row*132 + c4];
        const __half2 h01 = *(const __half2*)&Chs[row*132 + c4];
        const __half2 h23 = *(const __half2*)&Chs[row*132 + c4 + 2];
        v.x += __half2float(__low2half(h01));  v.y += __half2float(__high2half(h01));
        v.z += __half2float(__low2half(h23));  v.w += __half2float(__high2half(h23));
        const int gn = n0 + c4;
        if (MODE == 0) {
            if (gn < 2*CH) {  // q and k columns get elu+1 and scale
                v.x = featf(v.x); v.y = featf(v.y); v.z = featf(v.z); v.w = featf(v.w);
            }
        } else {
            v.x += bias[gn]; v.y += bias[gn+1]; v.z += bias[gn+2]; v.w += bias[gn+3];
        }
        *(float4*)&Cp[(size_t)(m0 + row)*NC + gn] = v;
    }
}

// ------------------------- kv = k^T v partials + ksum partials -------------------------
__global__ void __launch_bounds__(256) kv_partial_kernel() {
    const int s  = blockIdx.x;
    const int bh = blockIdx.y;
    const int b = bh >> 4, h = bh & 15;
    const int tid = threadIdx.x;
    const int d  = tid >> 2;
    const int e0 = (tid & 3) << 4;

    __shared__ __align__(16) float ks_[8][64];
    __shared__ __align__(16) float vs_[8][64];

    float acc[16];
    #pragma unroll
    for (int i = 0; i < 16; i++) acc[i] = 0.0f;
    float ksum = 0.0f;

    const float* kbase = g_qkv + (size_t)(b*SEQ)*NQKV + CH + h*DH;
    const float* vbase = kbase + CH;
    int nbase = s * (SEQ / NSPLIT);
    for (int it = 0; it < 32; ++it, nbase += 8) {
        #pragma unroll
        for (int j = 0; j < 2; ++j) {
            const int idx = tid + j*256;
            const int r = idx >> 6, c = idx & 63;
            ks_[r][c] = kbase[(size_t)(nbase + r)*NQKV + c];
            vs_[r][c] = vbase[(size_t)(nbase + r)*NQKV + c];
        }
        __syncthreads();
        #pragma unroll
        for (int r = 0; r < 8; ++r) {
            const float kd = ks_[r][d];
            ksum += kd;
            #pragma unroll
            for (int j4 = 0; j4 < 4; ++j4) {
                const float4 vv = *(const float4*)&vs_[r][e0 + j4*4];
                acc[j4*4+0] += kd*vv.x; acc[j4*4+1] += kd*vv.y;
                acc[j4*4+2] += kd*vv.z; acc[j4*4+3] += kd*vv.w;
            }
        }
        __syncthreads();
    }
    float* outp = g_kv_part + ((size_t)s*BHCNT + bh)*(DH*DH) + d*DH + e0;
    #pragma unroll
    for (int j4 = 0; j4 < 4; ++j4)
        *(float4*)&outp[j4*4] = make_float4(acc[j4*4], acc[j4*4+1], acc[j4*4+2], acc[j4*4+3]);
    if ((tid & 3) == 0)
        g_ksum_part[((size_t)s*BHCNT + bh)*DH + d] = ksum;
}

__global__ void kv_reduce_kernel() {
    const int i = blockIdx.x * 256 + threadIdx.x;
    float s = 0.0f;
    #pragma unroll
    for (int p = 0; p < NSPLIT; ++p) s += g_kv_part[(size_t)p*(BHCNT*DH*DH) + i];
    g_kv[i] = s;
}

// ------------------------- ksum reduce + denom^-1 -------------------------
__global__ void __launch_bounds__(256) denom_kernel() {
    const int bh = blockIdx.y;
    const int b = bh >> 4, h = bh & 15;
    const int tid = threadIdx.x;
    __shared__ float ksum_s[64];
    if (tid < 64) {
        float s = 0.0f;
        #pragma unroll
        for (int p = 0; p < NSPLIT; ++p) s += g_ksum_part[((size_t)p*BHCNT + bh)*DH + tid];
        ksum_s[tid] = s;
    }
    __syncthreads();
    const int n = blockIdx.x * 256 + tid;
    const float* qp = g_qkv + (size_t)(b*SEQ + n)*NQKV + h*DH;
    float a = 0.0f;
    #pragma unroll
    for (int d4 = 0; d4 < DH; d4 += 4) {
        const float4 q4 = *(const float4*)&qp[d4];
        a += q4.x*ksum_s[d4] + q4.y*ksum_s[d4+1] + q4.z*ksum_s[d4+2] + q4.w*ksum_s[d4+3];
    }
    g_denom[(size_t)bh*SEQ + n] = 1.0f / (a + 1e-6f);
}

// ------------------------- out = (q @ kv) * denom^-1, split to fp16 hi/lo -------------------------
__global__ void __launch_bounds__(256) attn_kernel() {
    const int bh = blockIdx.y;
    const int chunk = blockIdx.x;
    const int b = bh >> 4, h = bh & 15;
    const int tid = threadIdx.x;
    const int base = chunk * 64;

    __shared__ __align__(16) float kv_s[64*64];
    __shared__ float q_s[64*65];
    __shared__ float inv_s[64];

    for (int i = tid; i < DH*DH; i += 256) kv_s[i] = g_kv[(size_t)bh*(DH*DH) + i];
    for (int i = tid; i < 64*64; i += 256) {
        const int r = i >> 6, d = i & 63;
        q_s[r*65 + d] = g_qkv[(size_t)(b*SEQ + base + r)*NQKV + h*DH + d];
    }
    if (tid < 64) inv_s[tid] = g_denom[(size_t)bh*SEQ + base + tid];
    __syncthreads();

    const int rsub = tid >> 4;
    const int e4   = (tid & 15) << 2;
    #pragma unroll
    for (int p = 0; p < 4; ++p) {
        const int row = p*16 + rsub;
        float4 acc = make_float4(0.f, 0.f, 0.f, 0.f);
        #pragma unroll 8
        for (int d = 0; d < DH; ++d) {
            const float qv = q_s[row*65 + d];
            const float4 kvv = *(const float4*)&kv_s[d*DH + e4];
            acc.x += qv*kvv.x; acc.y += qv*kvv.y; acc.z += qv*kvv.z; acc.w += qv*kvv.w;
        }
        const float inv = inv_s[row];
        float a4[4] = {acc.x*inv, acc.y*inv, acc.z*inv, acc.w*inv};
        __half hv[4], lv[4];
        #pragma unroll
        for (int i = 0; i < 4; i++) {
            hv[i] = __float2half(a4[i]);
            lv[i] = __float2half(a4[i] - __half2float(hv[i]));
        }
        const size_t off = (size_t)(b*SEQ + base + row)*CH + h*DH + e4;
        *(__half2*)(g_attn_hi + off)     = __halves2half2(hv[0], hv[1]);
        *(__half2*)(g_attn_hi + off + 2) = __halves2half2(hv[2], hv[3]);
        *(__half2*)(g_attn_lo + off)     = __halves2half2(lv[0], lv[1]);
        *(__half2*)(g_attn_lo + off + 2) = __halves2half2(lv[2], lv[3]);
    }
}

// ------------------------- launch -------------------------
extern "C" void kernel_launch(void* const* d_in, const int* in_sizes, int n_in,
                              void* d_out, int out_size) {
    (void)in_sizes; (void)n_in; (void)out_size;
    const float* x     = (const float*)d_in[0];
    const float* w_qkv = (const float*)d_in[1];
    const float* w_out = (const float*)d_in[2];
    const float* b_out = (const float*)d_in[3];
    float* out = (float*)d_out;

    split_kernel<<<4096, 256>>>(x,     MROWS*KDIM, 0);
    split_kernel<<<2048, 256>>>(w_qkv, NQKV*KDIM,  1);
    split_kernel<<<1024, 256>>>(w_out, CH*KDIM,    2);

    cudaFuncSetAttribute(gemm_f16x3<0>, cudaFuncAttributeMaxDynamicSharedMemorySize, (int)GEMM_SMEM);
    gemm_f16x3<0><<<dim3(NQKV/BN, MROWS/BM), 256, GEMM_SMEM>>>(nullptr, nullptr);

    kv_partial_kernel<<<dim3(NSPLIT, BHCNT), 256>>>();
    kv_reduce_kernel<<<(BHCNT*DH*DH)/256, 256>>>();
    denom_kernel<<<dim3(SEQ/256, BHCNT), 256>>>();
    attn_kernel<<<dim3(SEQ/64, BHCNT), 256>>>();

    cudaFuncSetAttribute(gemm_f16x3<1>, cudaFuncAttributeMaxDynamicSharedMemorySize, (int)GEMM_SMEM);
    gemm_f16x3<1><<<dim3(CH/BN, MROWS/BM), 256, GEMM_SMEM>>>(out, b_out);
}

// round 11
// speedup vs baseline: 2.3884x; 1.2531x over previous
#include <cuda_runtime.h>
#include <cuda_fp16.h>
#include <mma.h>
#include <cstdint>

using namespace nvcuda;

#define BATCH 4
#define SEQ   4096
#define CH    1024
#define NHEAD 16
#define DH    64
#define MROWS (BATCH*SEQ)     /* 16384 */
#define KDIM  CH              /* 1024  */
#define NQKV  (3*CH)          /* 3072  */
#define NSPLIT 16
#define BHCNT (BATCH*NHEAD)   /* 64    */

// GEMM tiling
#define BM 128
#define BN 128
#define BK 32
#define NT (KDIM/BK)            /* 32 K-tiles */
#define STAGES 4
#define LDA 40                  /* half elems; 80 B row stride (16B-aligned) */
#define ARR_BYTES (128*LDA*2)   /* 10240 B per array (Ah/Bh/Bl)             */
#define STAGE_BYTES (3*ARR_BYTES)          /* 30720  */
#define GEMM_SMEM (STAGES*STAGE_BYTES)     /* 122880 */

// ------------------------- scratch (device globals; no allocs) -------------------------
__device__ __half g_xh[(size_t)MROWS*KDIM];
__device__ __half g_wqkv_hi[(size_t)NQKV*KDIM];
__device__ __half g_wqkv_lo[(size_t)NQKV*KDIM];
__device__ __half g_wout_hi[(size_t)CH*KDIM];
__device__ __half g_wout_lo[(size_t)CH*KDIM];
__device__ float  g_qkv[(size_t)MROWS*NQKV];
__device__ float  g_kv_part[(size_t)NSPLIT*BHCNT*DH*DH];
__device__ float  g_ksum_part[(size_t)NSPLIT*BHCNT*DH];
__device__ float  g_kv[(size_t)BHCNT*DH*DH];
__device__ float  g_denom[(size_t)BHCNT*SEQ];
__device__ __half g_attn_h[(size_t)MROWS*CH];

// ------------------------- helpers -------------------------
__device__ __forceinline__ uint32_t smem_u32(const void* p) {
    uint32_t a;
    asm("{ .reg .u64 t; cvta.to.shared.u64 t, %1; cvt.u32.u64 %0, t; }" : "=r"(a) : "l"(p));
    return a;
}
__device__ __forceinline__ void cp_async16(uint32_t s, const void* g) {
    asm volatile("cp.async.cg.shared.global [%0], [%1], 16;" :: "r"(s), "l"(g) : "memory");
}
__device__ __forceinline__ void cp_commit() {
    asm volatile("cp.async.commit_group;" ::: "memory");
}
template<int N>
__device__ __forceinline__ void cp_wait() {
    asm volatile("cp.async.wait_group %0;" :: "n"(N) : "memory");
}
__device__ __forceinline__ float featf(float x) {
    const float s = 0.35355339059327373f;       // 64^-0.25
    return (x > 0.0f) ? (x + 1.0f) * s : __expf(x) * s;
}

// ------------------------- fp32 -> fp16 convert (A side, hi only) -------------------------
__global__ void cvt_kernel(const float* __restrict__ src, __half* __restrict__ dst, int n) {
    int i = blockIdx.x * blockDim.x + threadIdx.x;
    int stride = gridDim.x * blockDim.x;
    for (; i < n; i += stride) dst[i] = __float2half(src[i]);
}

// ------------------------- fp32 -> fp16 hi/lo split (B side) -------------------------
__global__ void split_kernel(const float* __restrict__ src, int n, int mode) {
    __half *hi, *lo;
    if (mode == 0) { hi = g_wqkv_hi; lo = g_wqkv_lo; }
    else           { hi = g_wout_hi; lo = g_wout_lo; }
    int i = blockIdx.x * blockDim.x + threadIdx.x;
    int stride = gridDim.x * blockDim.x;
    for (; i < n; i += stride) {
        float v = src[i];
        __half h = __float2half(v);
        float r = v - __half2float(h);
        hi[i] = h;
        lo[i] = __float2half(r);
    }
}

// ------------------------- fp16x2 GEMM: C[m,n] = sum_k A[m,k]*B[n,k] -------------------------
// C ~= Ah*Bh (f32 acc) + Ah*Bl (f16 acc).  MODE 0: x @ wqkv^T -> g_qkv (feat on q,k cols).
// MODE 1: attn @ wout^T + bias -> Cout.
template<int MODE>
__global__ void __launch_bounds__(256) gemm_f16x2(float* __restrict__ CoutExt,
                                                  const float* __restrict__ bias) {
    constexpr int NC = (MODE == 0) ? NQKV : CH;
    const __half* __restrict__ Ah  = (MODE == 0) ? g_xh      : g_attn_h;
    const __half* __restrict__ Bhi = (MODE == 0) ? g_wqkv_hi : g_wout_hi;
    const __half* __restrict__ Blo = (MODE == 0) ? g_wqkv_lo : g_wout_lo;
    float* __restrict__ Cp = (MODE == 0) ? g_qkv : CoutExt;

    extern __shared__ __align__(16) char smem_raw[];
    const uint32_t sb = smem_u32(smem_raw);

    const int tid = threadIdx.x;
    const int wid = tid >> 5;
    const int wm_ = wid >> 1;    // 0..3 (M dir, 32 rows each)
    const int wn_ = wid & 1;     // 0..1 (N dir, 64 cols each)
    const int m0 = blockIdx.y * BM;
    const int n0 = blockIdx.x * BN;

    // Per-thread cp.async slots: 1536 16B-chunks per stage, 6 per thread.
    // idx = tid + j*256: arr = idx>>9 (0:Ah 1:Bh 2:Bl), r=(idx>>2)&127, c16=idx&3
    const char* gptr[6];
    uint32_t    sptr[6];
    #pragma unroll
    for (int j = 0; j < 6; ++j) {
        const int idx = tid + j * 256;
        const int arr = idx >> 9, r = (idx >> 2) & 127, c16 = idx & 3;
        const __half* base = (arr == 0) ? Ah : (arr == 1) ? Bhi : Blo;
        const int row = ((arr == 0) ? m0 : n0) + r;
        gptr[j] = (const char*)(base + (size_t)row * KDIM + c16 * 8);
        sptr[j] = sb + arr * ARR_BYTES + r * (LDA * 2) + c16 * 16;
    }

    wmma::fragment<wmma::accumulator,16,16,16,float>  accF[2][4];
    wmma::fragment<wmma::accumulator,16,16,16,__half> accH[2][4];
    #pragma unroll
    for (int i = 0; i < 2; i++)
        #pragma unroll
        for (int j = 0; j < 4; j++) {
            wmma::fill_fragment(accF[i][j], 0.0f);
            wmma::fill_fragment(accH[i][j], __float2half(0.0f));
        }

    // prologue: stages 0..STAGES-2
    #pragma unroll
    for (int s = 0; s < STAGES - 1; ++s) {
        const uint32_t so = (uint32_t)s * STAGE_BYTES;
        #pragma unroll
        for (int j = 0; j < 6; ++j) cp_async16(sptr[j] + so, gptr[j] + (size_t)s * (BK*2));
        cp_commit();
    }

    for (int kt = 0; kt < NT; ++kt) {
        cp_wait<STAGES - 2>();
        __syncthreads();

        const int ns = kt + STAGES - 1;
        if (ns < NT) {
            const uint32_t so = (uint32_t)(ns & (STAGES-1)) * STAGE_BYTES;
            #pragma unroll
            for (int j = 0; j < 6; ++j) cp_async16(sptr[j] + so, gptr[j] + (size_t)ns * (BK*2));
        }
        cp_commit();

        const __half* sA_h = (const __half*)(smem_raw + (size_t)(kt & (STAGES-1)) * STAGE_BYTES);
        const __half* sB_h = sA_h + 128*LDA;
        const __half* sB_l = sB_h + 128*LDA;
        const __half* pAh = sA_h + wm_*32*LDA;
        const __half* pBh = sB_h + wn_*64*LDA;
        const __half* pBl = sB_l + wn_*64*LDA;

        #pragma unroll
        for (int ks = 0; ks < BK; ks += 16) {
            wmma::fragment<wmma::matrix_a,16,16,16,__half,wmma::row_major> ah[2];
            wmma::load_matrix_sync(ah[0], pAh + ks, LDA);
            wmma::load_matrix_sync(ah[1], pAh + 16*LDA + ks, LDA);
            #pragma unroll
            for (int j = 0; j < 4; j++) {
                wmma::fragment<wmma::matrix_b,16,16,16,__half,wmma::col_major> bh, bl;
                wmma::load_matrix_sync(bh, pBh + j*16*LDA + ks, LDA);
                wmma::load_matrix_sync(bl, pBl + j*16*LDA + ks, LDA);
                wmma::mma_sync(accF[0][j], ah[0], bh, accF[0][j]);
                wmma::mma_sync(accF[1][j], ah[1], bh, accF[1][j]);
                wmma::mma_sync(accH[0][j], ah[0], bl, accH[0][j]);
                wmma::mma_sync(accH[1][j], ah[1], bl, accH[1][j]);
            }
        }
        __syncthreads();
    }
    cp_wait<0>();
    __syncthreads();

    // epilogue: stage f32 + f16 accumulators into smem, merge on global store
    float*  Cs  = (float*)smem_raw;                  // 128 x 132 f32 = 67584 B
    __half* Chs = (__half*)(smem_raw + 67584);       // 128 x 132 f16 = 33792 B
    #pragma unroll
    for (int i = 0; i < 2; i++)
        #pragma unroll
        for (int j = 0; j < 4; j++) {
            wmma::store_matrix_sync(Cs  + (wm_*32 + i*16)*132 + wn_*64 + j*16,
                                    accF[i][j], 132, wmma::mem_row_major);
            wmma::store_matrix_sync(Chs + (wm_*32 + i*16)*132 + wn_*64 + j*16,
                                    accH[i][j], 132, wmma::mem_row_major);
        }
    __syncthreads();
    for (int i = tid; i < BM*BN/4; i += 256) {
        const int row = i >> 5;
        const int c4  = (i & 31) << 2;
        float4 v = *(const float4*)&Cs[row*132 + c4];
        const __half2 h01 = *(const __half2*)&Chs[row*132 + c4];
        const __half2 h23 = *(const __half2*)&Chs[row*132 + c4 + 2];
        v.x += __half2float(__low2half(h01));  v.y += __half2float(__high2half(h01));
        v.z += __half2float(__low2half(h23));  v.w += __half2float(__high2half(h23));
        const int gn = n0 + c4;
        if (MODE == 0) {
            if (gn < 2*CH) {  // q and k columns get elu+1 and scale
                v.x = featf(v.x); v.y = featf(v.y); v.z = featf(v.z); v.w = featf(v.w);
            }
        } else {
            v.x += bias[gn]; v.y += bias[gn+1]; v.z += bias[gn+2]; v.w += bias[gn+3];
        }
        *(float4*)&Cp[(size_t)(m0 + row)*NC + gn] = v;
    }
}

// ------------------------- kv = k^T v partials + ksum partials -------------------------
__global__ void __launch_bounds__(256) kv_partial_kernel() {
    const int s  = blockIdx.x;
    const int bh = blockIdx.y;
    const int b = bh >> 4, h = bh & 15;
    const int tid = threadIdx.x;
    const int d  = tid >> 2;
    const int e0 = (tid & 3) << 4;

    __shared__ __align__(16) float ks_[8][64];
    __shared__ __align__(16) float vs_[8][64];

    float acc[16];
    #pragma unroll
    for (int i = 0; i < 16; i++) acc[i] = 0.0f;
    float ksum = 0.0f;

    const float* kbase = g_qkv + (size_t)(b*SEQ)*NQKV + CH + h*DH;
    const float* vbase = kbase + CH;
    int nbase = s * (SEQ / NSPLIT);
    for (int it = 0; it < 32; ++it, nbase += 8) {
        #pragma unroll
        for (int j = 0; j < 2; ++j) {
            const int idx = tid + j*256;
            const int r = idx >> 6, c = idx & 63;
            ks_[r][c] = kbase[(size_t)(nbase + r)*NQKV + c];
            vs_[r][c] = vbase[(size_t)(nbase + r)*NQKV + c];
        }
        __syncthreads();
        #pragma unroll
        for (int r = 0; r < 8; ++r) {
            const float kd = ks_[r][d];
            ksum += kd;
            #pragma unroll
            for (int j4 = 0; j4 < 4; ++j4) {
                const float4 vv = *(const float4*)&vs_[r][e0 + j4*4];
                acc[j4*4+0] += kd*vv.x; acc[j4*4+1] += kd*vv.y;
                acc[j4*4+2] += kd*vv.z; acc[j4*4+3] += kd*vv.w;
            }
        }
        __syncthreads();
    }
    float* outp = g_kv_part + ((size_t)s*BHCNT + bh)*(DH*DH) + d*DH + e0;
    #pragma unroll
    for (int j4 = 0; j4 < 4; ++j4)
        *(float4*)&outp[j4*4] = make_float4(acc[j4*4], acc[j4*4+1], acc[j4*4+2], acc[j4*4+3]);
    if ((tid & 3) == 0)
        g_ksum_part[((size_t)s*BHCNT + bh)*DH + d] = ksum;
}

__global__ void kv_reduce_kernel() {
    const int i = blockIdx.x * 256 + threadIdx.x;
    float s = 0.0f;
    #pragma unroll
    for (int p = 0; p < NSPLIT; ++p) s += g_kv_part[(size_t)p*(BHCNT*DH*DH) + i];
    g_kv[i] = s;
}

// ------------------------- ksum reduce + denom^-1 -------------------------
__global__ void __launch_bounds__(256) denom_kernel() {
    const int bh = blockIdx.y;
    const int b = bh >> 4, h = bh & 15;
    const int tid = threadIdx.x;
    __shared__ float ksum_s[64];
    if (tid < 64) {
        float s = 0.0f;
        #pragma unroll
        for (int p = 0; p < NSPLIT; ++p) s += g_ksum_part[((size_t)p*BHCNT + bh)*DH + tid];
        ksum_s[tid] = s;
    }
    __syncthreads();
    const int n = blockIdx.x * 256 + tid;
    const float* qp = g_qkv + (size_t)(b*SEQ + n)*NQKV + h*DH;
    float a = 0.0f;
    #pragma unroll
    for (int d4 = 0; d4 < DH; d4 += 4) {
        const float4 q4 = *(const float4*)&qp[d4];
        a += q4.x*ksum_s[d4] + q4.y*ksum_s[d4+1] + q4.z*ksum_s[d4+2] + q4.w*ksum_s[d4+3];
    }
    g_denom[(size_t)bh*SEQ + n] = 1.0f / (a + 1e-6f);
}

// ------------------------- out = (q @ kv) * denom^-1 -> fp16 -------------------------
__global__ void __launch_bounds__(256) attn_kernel() {
    const int bh = blockIdx.y;
    const int chunk = blockIdx.x;
    const int b = bh >> 4, h = bh & 15;
    const int tid = threadIdx.x;
    const int base = chunk * 64;

    __shared__ __align__(16) float kv_s[64*64];
    __shared__ float q_s[64*65];
    __shared__ float inv_s[64];

    for (int i = tid; i < DH*DH; i += 256) kv_s[i] = g_kv[(size_t)bh*(DH*DH) + i];
    for (int i = tid; i < 64*64; i += 256) {
        const int r = i >> 6, d = i & 63;
        q_s[r*65 + d] = g_qkv[(size_t)(b*SEQ + base + r)*NQKV + h*DH + d];
    }
    if (tid < 64) inv_s[tid] = g_denom[(size_t)bh*SEQ + base + tid];
    __syncthreads();

    const int rsub = tid >> 4;
    const int e4   = (tid & 15) << 2;
    #pragma unroll
    for (int p = 0; p < 4; ++p) {
        const int row = p*16 + rsub;
        float4 acc = make_float4(0.f, 0.f, 0.f, 0.f);
        #pragma unroll 8
        for (int d = 0; d < DH; ++d) {
            const float qv = q_s[row*65 + d];
            const float4 kvv = *(const float4*)&kv_s[d*DH + e4];
            acc.x += qv*kvv.x; acc.y += qv*kvv.y; acc.z += qv*kvv.z; acc.w += qv*kvv.w;
        }
        const float inv = inv_s[row];
        const size_t off = (size_t)(b*SEQ + base + row)*CH + h*DH + e4;
        *(__half2*)(g_attn_h + off)     = __halves2half2(__float2half(acc.x*inv), __float2half(acc.y*inv));
        *(__half2*)(g_attn_h + off + 2) = __halves2half2(__float2half(acc.z*inv), __float2half(acc.w*inv));
    }
}

// ------------------------- launch -------------------------
extern "C" void kernel_launch(void* const* d_in, const int* in_sizes, int n_in,
                              void* d_out, int out_size) {
    (void)in_sizes; (void)n_in; (void)out_size;
    const float* x     = (const float*)d_in[0];
    const float* w_qkv = (const float*)d_in[1];
    const float* w_out = (const float*)d_in[2];
    const float* b_out = (const float*)d_in[3];
    float* out = (float*)d_out;

    __half* xh;
    cudaGetSymbolAddress((void**)&xh, g_xh);

    cvt_kernel<<<4096, 256>>>(x, xh, MROWS*KDIM);
    split_kernel<<<2048, 256>>>(w_qkv, NQKV*KDIM, 0);
    split_kernel<<<1024, 256>>>(w_out, CH*KDIM,   1);

    cudaFuncSetAttribute(gemm_f16x2<0>, cudaFuncAttributeMaxDynamicSharedMemorySize, (int)GEMM_SMEM);
    gemm_f16x2<0><<<dim3(NQKV/BN, MROWS/BM), 256, GEMM_SMEM>>>(nullptr, nullptr);

    kv_partial_kernel<<<dim3(NSPLIT, BHCNT), 256>>>();
    kv_reduce_kernel<<<(BHCNT*DH*DH)/256, 256>>>();
    denom_kernel<<<dim3(SEQ/256, BHCNT), 256>>>();
    attn_kernel<<<dim3(SEQ/64, BHCNT), 256>>>();

    cudaFuncSetAttribute(gemm_f16x2<1>, cudaFuncAttributeMaxDynamicSharedMemorySize, (int)GEMM_SMEM);
    gemm_f16x2<1><<<dim3(CH/BN, MROWS/BM), 256, GEMM_SMEM>>>(out, b_out);
}

// round 13
// speedup vs baseline: 2.3997x; 1.0047x over previous
#include <cuda_runtime.h>
#include <cuda_fp16.h>
#include <mma.h>
#include <cstdint>

using namespace nvcuda;

#define BATCH 4
#define SEQ   4096
#define CH    1024
#define NHEAD 16
#define DH    64
#define MROWS (BATCH*SEQ)     /* 16384 */
#define KDIM  CH              /* 1024  */
#define NQKV  (3*CH)          /* 3072  */
#define NSPLIT 16
#define BHCNT (BATCH*NHEAD)   /* 64    */

// GEMM tiling
#define BM 128
#define BN 128
#define BK 32
#define NT (KDIM/BK)            /* 32 K-tiles */
#define STAGES 4
#define LDA 40                  /* half elems; 80 B row stride (16B-aligned) */
#define ARR_BYTES (128*LDA*2)   /* 10240 B per array (Ah/Bh/Bl)             */
#define STAGE_BYTES (3*ARR_BYTES)          /* 30720  */
#define GEMM_SMEM (STAGES*STAGE_BYTES)     /* 122880 */

// ------------------------- scratch (device globals; no allocs) -------------------------
__device__ __half g_xh[(size_t)MROWS*KDIM];
__device__ __half g_wqkv_hi[(size_t)NQKV*KDIM];
__device__ __half g_wqkv_lo[(size_t)NQKV*KDIM];
__device__ __half g_wout_hi[(size_t)CH*KDIM];
__device__ __half g_wout_lo[(size_t)CH*KDIM];
__device__ __half g_qkvh[(size_t)MROWS*NQKV];          // q,k (feat applied), v — fp16
__device__ float  g_kv_part[(size_t)NSPLIT*BHCNT*DH*DH];
__device__ float  g_ksum_part[(size_t)NSPLIT*BHCNT*DH];
__device__ float  g_kv[(size_t)BHCNT*DH*DH];
__device__ __half g_attn_h[(size_t)MROWS*CH];

// ------------------------- helpers -------------------------
__device__ __forceinline__ uint32_t smem_u32(const void* p) {
    uint32_t a;
    asm("{ .reg .u64 t; cvta.to.shared.u64 t, %1; cvt.u32.u64 %0, t; }" : "=r"(a) : "l"(p));
    return a;
}
__device__ __forceinline__ void cp_async16(uint32_t s, const void* g) {
    asm volatile("cp.async.cg.shared.global [%0], [%1], 16;" :: "r"(s), "l"(g) : "memory");
}
__device__ __forceinline__ void cp_commit() {
    asm volatile("cp.async.commit_group;" ::: "memory");
}
template<int N>
__device__ __forceinline__ void cp_wait() {
    asm volatile("cp.async.wait_group %0;" :: "n"(N) : "memory");
}
__device__ __forceinline__ float featf(float x) {
    const float s = 0.35355339059327373f;       // 64^-0.25
    return (x > 0.0f) ? (x + 1.0f) * s : __expf(x) * s;
}

// ------------------------- fp32 -> fp16 convert (A side, hi only) -------------------------
__global__ void cvt_kernel(const float* __restrict__ src, __half* __restrict__ dst, int n) {
    int i = blockIdx.x * blockDim.x + threadIdx.x;
    int stride = gridDim.x * blockDim.x;
    for (; i < n; i += stride) dst[i] = __float2half(src[i]);
}

// ------------------------- fp32 -> fp16 hi/lo split (B side) -------------------------
__global__ void split_kernel(const float* __restrict__ src, int n, int mode) {
    __half *hi, *lo;
    if (mode == 0) { hi = g_wqkv_hi; lo = g_wqkv_lo; }
    else           { hi = g_wout_hi; lo = g_wout_lo; }
    int i = blockIdx.x * blockDim.x + threadIdx.x;
    int stride = gridDim.x * blockDim.x;
    for (; i < n; i += stride) {
        float v = src[i];
        __half h = __float2half(v);
        float r = v - __half2float(h);
        hi[i] = h;
        lo[i] = __float2half(r);
    }
}

// ------------------------- fp16x2 GEMM: C[m,n] = sum_k A[m,k]*B[n,k] -------------------------
// C ~= Ah*Bh (f32 acc) + Ah*Bl (f16 acc). Warp tile 64(M) x 32(N): 8 ldmatrix / 16 MMA.
// MODE 0: x @ wqkv^T -> g_qkvh fp16 (feat on q,k cols). MODE 1: attn @ wout^T + bias -> fp32 out.
template<int MODE>
__global__ void __launch_bounds__(256) gemm_f16x2(float* __restrict__ CoutExt,
                                                  const float* __restrict__ bias) {
    const __half* __restrict__ Ah  = (MODE == 0) ? g_xh      : g_attn_h;
    const __half* __restrict__ Bhi = (MODE == 0) ? g_wqkv_hi : g_wout_hi;
    const __half* __restrict__ Blo = (MODE == 0) ? g_wqkv_lo : g_wout_lo;

    extern __shared__ __align__(16) char smem_raw[];
    const uint32_t sb = smem_u32(smem_raw);

    const int tid = threadIdx.x;
    const int wid = tid >> 5;
    const int wm_ = wid >> 2;    // 0..1 (M dir, 64 rows each)
    const int wn_ = wid & 3;     // 0..3 (N dir, 32 cols each)
    const int m0 = blockIdx.y * BM;
    const int n0 = blockIdx.x * BN;

    // Per-thread cp.async slots: 1536 16B-chunks per stage, 6 per thread.
    const char* gptr[6];
    uint32_t    sptr[6];
    #pragma unroll
    for (int j = 0; j < 6; ++j) {
        const int idx = tid + j * 256;
        const int arr = idx >> 9, r = (idx >> 2) & 127, c16 = idx & 3;
        const __half* base = (arr == 0) ? Ah : (arr == 1) ? Bhi : Blo;
        const int row = ((arr == 0) ? m0 : n0) + r;
        gptr[j] = (const char*)(base + (size_t)row * KDIM + c16 * 8);
        sptr[j] = sb + arr * ARR_BYTES + r * (LDA * 2) + c16 * 16;
    }

    wmma::fragment<wmma::accumulator,16,16,16,float>  accF[4][2];
    wmma::fragment<wmma::accumulator,16,16,16,__half> accH[4][2];
    #pragma unroll
    for (int i = 0; i < 4; i++)
        #pragma unroll
        for (int j = 0; j < 2; j++) {
            wmma::fill_fragment(accF[i][j], 0.0f);
            wmma::fill_fragment(accH[i][j], __float2half(0.0f));
        }

    // prologue: stages 0..STAGES-2
    #pragma unroll
    for (int s = 0; s < STAGES - 1; ++s) {
        const uint32_t so = (uint32_t)s * STAGE_BYTES;
        #pragma unroll
        for (int j = 0; j < 6; ++j) cp_async16(sptr[j] + so, gptr[j] + (size_t)s * (BK*2));
        cp_commit();
    }

    for (int kt = 0; kt < NT; ++kt) {
        cp_wait<STAGES - 2>();
        __syncthreads();

        const int ns = kt + STAGES - 1;
        if (ns < NT) {
            const uint32_t so = (uint32_t)(ns & (STAGES-1)) * STAGE_BYTES;
            #pragma unroll
            for (int j = 0; j < 6; ++j) cp_async16(sptr[j] + so, gptr[j] + (size_t)ns * (BK*2));
        }
        cp_commit();

        const __half* sA_h = (const __half*)(smem_raw + (size_t)(kt & (STAGES-1)) * STAGE_BYTES);
        const __half* sB_h = sA_h + 128*LDA;
        const __half* sB_l = sB_h + 128*LDA;
        const __half* pAh = sA_h + wm_*64*LDA;
        const __half* pBh = sB_h + wn_*32*LDA;
        const __half* pBl = sB_l + wn_*32*LDA;

        #pragma unroll
        for (int ks = 0; ks < BK; ks += 16) {
            wmma::fragment<wmma::matrix_a,16,16,16,__half,wmma::row_major> ah[4];
            wmma::fragment<wmma::matrix_b,16,16,16,__half,wmma::col_major> bh[2], bl[2];
            #pragma unroll
            for (int i = 0; i < 4; i++) wmma::load_matrix_sync(ah[i], pAh + i*16*LDA + ks, LDA);
            #pragma unroll
            for (int j = 0; j < 2; j++) {
                wmma::load_matrix_sync(bh[j], pBh + j*16*LDA + ks, LDA);
                wmma::load_matrix_sync(bl[j], pBl + j*16*LDA + ks, LDA);
            }
            #pragma unroll
            for (int i = 0; i < 4; i++)
                #pragma unroll
                for (int j = 0; j < 2; j++) wmma::mma_sync(accF[i][j], ah[i], bh[j], accF[i][j]);
            #pragma unroll
            for (int i = 0; i < 4; i++)
                #pragma unroll
                for (int j = 0; j < 2; j++) wmma::mma_sync(accH[i][j], ah[i], bl[j], accH[i][j]);
        }
        __syncthreads();
    }
    cp_wait<0>();
    __syncthreads();

    // epilogue: stage f32 + f16 accumulators into smem, merge on store
    float*  Cs  = (float*)smem_raw;                  // 128 x 132 f32 = 67584 B
    __half* Chs = (__half*)(smem_raw + 67584);       // 128 x 132 f16 = 33792 B
    #pragma unroll
    for (int i = 0; i < 4; i++)
        #pragma unroll
        for (int j = 0; j < 2; j++) {
            wmma::store_matrix_sync(Cs  + (wm_*64 + i*16)*132 + wn_*32 + j*16,
                                    accF[i][j], 132, wmma::mem_row_major);
            wmma::store_matrix_sync(Chs + (wm_*64 + i*16)*132 + wn_*32 + j*16,
                                    accH[i][j], 132, wmma::mem_row_major);
        }
    __syncthreads();
    for (int i = tid; i < BM*BN/4; i += 256) {
        const int row = i >> 5;
        const int c4  = (i & 31) << 2;
        float4 v = *(const float4*)&Cs[row*132 + c4];
        const __half2 h01 = *(const __half2*)&Chs[row*132 + c4];
        const __half2 h23 = *(const __half2*)&Chs[row*132 + c4 + 2];
        v.x += __half2float(__low2half(h01));  v.y += __half2float(__high2half(h01));
        v.z += __half2float(__low2half(h23));  v.w += __half2float(__high2half(h23));
        const int gn = n0 + c4;
        if (MODE == 0) {
            if (gn < 2*CH) {  // q and k columns get elu+1 and scale
                v.x = featf(v.x); v.y = featf(v.y); v.z = featf(v.z); v.w = featf(v.w);
            }
            __half2 o01 = __halves2half2(__float2half(v.x), __float2half(v.y));
            __half2 o23 = __halves2half2(__float2half(v.z), __float2half(v.w));
            __half* dst = g_qkvh + (size_t)(m0 + row)*NQKV + gn;
            *(__half2*)dst       = o01;
            *(__half2*)(dst + 2) = o23;
        } else {
            v.x += bias[gn]; v.y += bias[gn+1]; v.z += bias[gn+2]; v.w += bias[gn+3];
            *(float4*)&CoutExt[(size_t)(m0 + row)*CH + gn] = v;
        }
    }
}

// ------------------------- kv = k^T v partials + ksum partials (fp16 inputs) -------------------------
__global__ void __launch_bounds__(256) kv_partial_kernel() {
    const int s  = blockIdx.x;
    const int bh = blockIdx.y;
    const int b = bh >> 4, h = bh & 15;
    const int tid = threadIdx.x;
    const int d  = tid >> 2;
    const int e0 = (tid & 3) << 4;

    __shared__ __align__(16) float ks_[8][64];
    __shared__ __align__(16) float vs_[8][64];

    float acc[16];
    #pragma unroll
    for (int i = 0; i < 16; i++) acc[i] = 0.0f;
    float ksum = 0.0f;

    const __half* kbase = g_qkvh + (size_t)(b*SEQ)*NQKV + CH + h*DH;
    const __half* vbase = kbase + CH;
    int nbase = s * (SEQ / NSPLIT);
    const int r = tid >> 5, c2 = (tid & 31) * 2;    // 8 rows x 32 half2 = 512 halves
    for (int it = 0; it < 32; ++it, nbase += 8) {
        {
            const size_t go = (size_t)(nbase + r)*NQKV + c2;
            const __half2 kk = *(const __half2*)&kbase[go];
            const __half2 vv = *(const __half2*)&vbase[go];
            ks_[r][c2]   = __half2float(__low2half(kk));
            ks_[r][c2+1] = __half2float(__high2half(kk));
            vs_[r][c2]   = __half2float(__low2half(vv));
            vs_[r][c2+1] = __half2float(__high2half(vv));
        }
        __syncthreads();
        #pragma unroll
        for (int rr = 0; rr < 8; ++rr) {
            const float kd = ks_[rr][d];
            ksum += kd;
            #pragma unroll
            for (int j4 = 0; j4 < 4; ++j4) {
                const float4 vv = *(const float4*)&vs_[rr][e0 + j4*4];
                acc[j4*4+0] += kd*vv.x; acc[j4*4+1] += kd*vv.y;
                acc[j4*4+2] += kd*vv.z; acc[j4*4+3] += kd*vv.w;
            }
        }
        __syncthreads();
    }
    float* outp = g_kv_part + ((size_t)s*BHCNT + bh)*(DH*DH) + d*DH + e0;
    #pragma unroll
    for (int j4 = 0; j4 < 4; ++j4)
        *(float4*)&outp[j4*4] = make_float4(acc[j4*4], acc[j4*4+1], acc[j4*4+2], acc[j4*4+3]);
    if ((tid & 3) == 0)
        g_ksum_part[((size_t)s*BHCNT + bh)*DH + d] = ksum;
}

__global__ void kv_reduce_kernel() {
    const int i = blockIdx.x * 256 + threadIdx.x;
    float s = 0.0f;
    #pragma unroll
    for (int p = 0; p < NSPLIT; ++p) s += g_kv_part[(size_t)p*(BHCNT*DH*DH) + i];
    g_kv[i] = s;
}

// ------------------------- out = (q @ kv) / (q . ksum + eps) -> fp16 (denom fused) -------------------------
__global__ void __launch_bounds__(256) attn_kernel() {
    const int bh = blockIdx.y;
    const int chunk = blockIdx.x;
    const int b = bh >> 4, h = bh & 15;
    const int tid = threadIdx.x;
    const int base = chunk * 64;

    __shared__ __align__(16) float kv_s[64*64];
    __shared__ float q_s[64*65];
    __shared__ float ksum_s[64];
    __shared__ float inv_s[64];

    for (int i = tid; i < DH*DH; i += 256) kv_s[i] = g_kv[(size_t)bh*(DH*DH) + i];
    for (int i = tid; i < 64*64; i += 256) {
        const int r = i >> 6, d = i & 63;
        q_s[r*65 + d] = __half2float(g_qkvh[(size_t)(b*SEQ + base + r)*NQKV + h*DH + d]);
    }
    if (tid < 64) {
        float s = 0.0f;
        #pragma unroll
        for (int p = 0; p < NSPLIT; ++p) s += g_ksum_part[((size_t)p*BHCNT + bh)*DH + tid];
        ksum_s[tid] = s;
    }
    __syncthreads();
    if (tid < 64) {     // denom per row, inline
        float a = 0.0f;
        #pragma unroll 16
        for (int d = 0; d < DH; ++d) a += q_s[tid*65 + d] * ksum_s[d];
        inv_s[tid] = 1.0f / (a + 1e-6f);
    }
    __syncthreads();

    const int rsub = tid >> 4;
    const int e4   = (tid & 15) << 2;
    #pragma unroll
    for (int p = 0; p < 4; ++p) {
        const int row = p*16 + rsub;
        float4 acc = make_float4(0.f, 0.f, 0.f, 0.f);
        #pragma unroll 8
        for (int d = 0; d < DH; ++d) {
            const float qv = q_s[row*65 + d];
            const float4 kvv = *(const float4*)&kv_s[d*DH + e4];
            acc.x += qv*kvv.x; acc.y += qv*kvv.y; acc.z += qv*kvv.z; acc.w += qv*kvv.w;
        }
        const float inv = inv_s[row];
        const size_t off = (size_t)(b*SEQ + base + row)*CH + h*DH + e4;
        *(__half2*)(g_attn_h + off)     = __halves2half2(__float2half(acc.x*inv), __float2half(acc.y*inv));
        *(__half2*)(g_attn_h + off + 2) = __halves2half2(__float2half(acc.z*inv), __float2half(acc.w*inv));
    }
}

// ------------------------- launch -------------------------
extern "C" void kernel_launch(void* const* d_in, const int* in_sizes, int n_in,
                              void* d_out, int out_size) {
    (void)in_sizes; (void)n_in; (void)out_size;
    const float* x     = (const float*)d_in[0];
    const float* w_qkv = (const float*)d_in[1];
    const float* w_out = (const float*)d_in[2];
    const float* b_out = (const float*)d_in[3];
    float* out = (float*)d_out;

    __half* xh;
    cudaGetSymbolAddress((void**)&xh, g_xh);

    cvt_kernel<<<4096, 256>>>(x, xh, MROWS*KDIM);
    split_kernel<<<2048, 256>>>(w_qkv, NQKV*KDIM, 0);
    split_kernel<<<1024, 256>>>(w_out, CH*KDIM,   1);

    cudaFuncSetAttribute(gemm_f16x2<0>, cudaFuncAttributeMaxDynamicSharedMemorySize, (int)GEMM_SMEM);
    gemm_f16x2<0><<<dim3(NQKV/BN, MROWS/BM), 256, GEMM_SMEM>>>(nullptr, nullptr);

    kv_partial_kernel<<<dim3(NSPLIT, BHCNT), 256>>>();
    kv_reduce_kernel<<<(BHCNT*DH*DH)/256, 256>>>();
    attn_kernel<<<dim3(SEQ/64, BHCNT), 256>>>();

    cudaFuncSetAttribute(gemm_f16x2<1>, cudaFuncAttributeMaxDynamicSharedMemorySize, (int)GEMM_SMEM);
    gemm_f16x2<1><<<dim3(CH/BN, MROWS/BM), 256, GEMM_SMEM>>>(out, b_out);
}

// round 14
// speedup vs baseline: 3.9000x; 1.6252x over previous
#include <cuda_runtime.h>
#include <cuda_fp16.h>
#include <mma.h>
#include <cstdint>

using namespace nvcuda;

#define BATCH 4
#define SEQ   4096
#define CH    1024
#define NHEAD 16
#define DH    64
#define MROWS (BATCH*SEQ)     /* 16384 */
#define KDIM  CH              /* 1024  */
#define NQKV  (3*CH)          /* 3072  */
#define NSPLIT 16
#define BHCNT (BATCH*NHEAD)   /* 64    */

// GEMM tiling
#define BM 128
#define BN 128
#define BK 32
#define NT (KDIM/BK)            /* 32 K-tiles */
#define STAGES 4
#define LDA 40                  /* half elems; 80 B row stride (16B-aligned) */
#define ARR_BYTES (128*LDA*2)   /* 10240 B per array (A/B)                  */
#define STAGE_BYTES (2*ARR_BYTES)          /* 20480 */
#define GEMM_SMEM (STAGES*STAGE_BYTES)     /* 81920 */

// ------------------------- scratch (device globals; no allocs) -------------------------
__device__ __half g_xh[(size_t)MROWS*KDIM];
__device__ __half g_wqkvh[(size_t)NQKV*KDIM];
__device__ __half g_wouth[(size_t)CH*KDIM];
__device__ __half g_qkvh[(size_t)MROWS*NQKV];          // q,k (feat applied), v — fp16
__device__ float  g_kv_part[(size_t)NSPLIT*BHCNT*DH*DH];
__device__ float  g_ksum_part[(size_t)NSPLIT*BHCNT*DH];
__device__ float  g_kv[(size_t)BHCNT*DH*DH];
__device__ __half g_attn_h[(size_t)MROWS*CH];

// ------------------------- helpers -------------------------
__device__ __forceinline__ uint32_t smem_u32(const void* p) {
    uint32_t a;
    asm("{ .reg .u64 t; cvta.to.shared.u64 t, %1; cvt.u32.u64 %0, t; }" : "=r"(a) : "l"(p));
    return a;
}
__device__ __forceinline__ void cp_async16(uint32_t s, const void* g) {
    asm volatile("cp.async.cg.shared.global [%0], [%1], 16;" :: "r"(s), "l"(g) : "memory");
}
__device__ __forceinline__ void cp_commit() {
    asm volatile("cp.async.commit_group;" ::: "memory");
}
template<int N>
__device__ __forceinline__ void cp_wait() {
    asm volatile("cp.async.wait_group %0;" :: "n"(N) : "memory");
}
__device__ __forceinline__ float featf(float x) {
    const float s = 0.35355339059327373f;       // 64^-0.25
    return (x > 0.0f) ? (x + 1.0f) * s : __expf(x) * s;
}

// ------------------------- fp32 -> fp16 convert -------------------------
__global__ void cvt_kernel(const float* __restrict__ src, __half* __restrict__ dst, int n) {
    int i = blockIdx.x * blockDim.x + threadIdx.x;
    int stride = gridDim.x * blockDim.x;
    for (; i < n; i += stride) dst[i] = __float2half(src[i]);
}

// ------------------------- fp16 GEMM: C[m,n] = sum_k A[m,k]*B[n,k], f32 acc -------------------------
// MODE 0: x @ wqkv^T -> g_qkvh fp16 (feat on q,k cols). MODE 1: attn @ wout^T + bias -> fp32 out.
template<int MODE>
__global__ void __launch_bounds__(256) gemm_f16(float* __restrict__ CoutExt,
                                                const float* __restrict__ bias) {
    const __half* __restrict__ Ah = (MODE == 0) ? g_xh    : g_attn_h;
    const __half* __restrict__ Bh = (MODE == 0) ? g_wqkvh : g_wouth;

    extern __shared__ __align__(16) char smem_raw[];
    const uint32_t sb = smem_u32(smem_raw);

    const int tid = threadIdx.x;
    const int wid = tid >> 5;
    const int wm_ = wid >> 2;    // 0..1 (M dir, 64 rows each)
    const int wn_ = wid & 3;     // 0..3 (N dir, 32 cols each)
    const int m0 = blockIdx.y * BM;
    const int n0 = blockIdx.x * BN;

    // Per-thread cp.async slots: 1024 16B-chunks per stage, 4 per thread.
    // idx = tid + j*256: arr = idx>>9 (0:A 1:B), r=(idx>>2)&127, c16=idx&3
    const char* gptr[4];
    uint32_t    sptr[4];
    #pragma unroll
    for (int j = 0; j < 4; ++j) {
        const int idx = tid + j * 256;
        const int arr = idx >> 9, r = (idx >> 2) & 127, c16 = idx & 3;
        const __half* base = (arr == 0) ? Ah : Bh;
        const int row = ((arr == 0) ? m0 : n0) + r;
        gptr[j] = (const char*)(base + (size_t)row * KDIM + c16 * 8);
        sptr[j] = sb + arr * ARR_BYTES + r * (LDA * 2) + c16 * 16;
    }

    wmma::fragment<wmma::accumulator,16,16,16,float> acc[4][2];
    #pragma unroll
    for (int i = 0; i < 4; i++)
        #pragma unroll
        for (int j = 0; j < 2; j++) wmma::fill_fragment(acc[i][j], 0.0f);

    // prologue: stages 0..STAGES-2
    #pragma unroll
    for (int s = 0; s < STAGES - 1; ++s) {
        const uint32_t so = (uint32_t)s * STAGE_BYTES;
        #pragma unroll
        for (int j = 0; j < 4; ++j) cp_async16(sptr[j] + so, gptr[j] + (size_t)s * (BK*2));
        cp_commit();
    }

    for (int kt = 0; kt < NT; ++kt) {
        cp_wait<STAGES - 2>();
        __syncthreads();

        const int ns = kt + STAGES - 1;
        if (ns < NT) {
            const uint32_t so = (uint32_t)(ns & (STAGES-1)) * STAGE_BYTES;
            #pragma unroll
            for (int j = 0; j < 4; ++j) cp_async16(sptr[j] + so, gptr[j] + (size_t)ns * (BK*2));
        }
        cp_commit();

        const __half* sA = (const __half*)(smem_raw + (size_t)(kt & (STAGES-1)) * STAGE_BYTES);
        const __half* sB = sA + 128*LDA;
        const __half* pA = sA + wm_*64*LDA;
        const __half* pB = sB + wn_*32*LDA;

        #pragma unroll
        for (int ks = 0; ks < BK; ks += 16) {
            wmma::fragment<wmma::matrix_a,16,16,16,__half,wmma::row_major> a[4];
            wmma::fragment<wmma::matrix_b,16,16,16,__half,wmma::col_major> b[2];
            #pragma unroll
            for (int i = 0; i < 4; i++) wmma::load_matrix_sync(a[i], pA + i*16*LDA + ks, LDA);
            #pragma unroll
            for (int j = 0; j < 2; j++) wmma::load_matrix_sync(b[j], pB + j*16*LDA + ks, LDA);
            #pragma unroll
            for (int i = 0; i < 4; i++)
                #pragma unroll
                for (int j = 0; j < 2; j++) wmma::mma_sync(acc[i][j], a[i], b[j], acc[i][j]);
        }
        __syncthreads();
    }
    cp_wait<0>();
    __syncthreads();

    // epilogue: stage accumulators in smem, fused feat/bias on store
    float* Cs = (float*)smem_raw;   // 128 x 132 f32 = 67584 B (fits in 81920)
    #pragma unroll
    for (int i = 0; i < 4; i++)
        #pragma unroll
        for (int j = 0; j < 2; j++)
            wmma::store_matrix_sync(Cs + (wm_*64 + i*16)*132 + wn_*32 + j*16,
                                    acc[i][j], 132, wmma::mem_row_major);
    __syncthreads();
    for (int i = tid; i < BM*BN/4; i += 256) {
        const int row = i >> 5;
        const int c4  = (i & 31) << 2;
        float4 v = *(const float4*)&Cs[row*132 + c4];
        const int gn = n0 + c4;
        if (MODE == 0) {
            if (gn < 2*CH) {  // q and k columns get elu+1 and scale
                v.x = featf(v.x); v.y = featf(v.y); v.z = featf(v.z); v.w = featf(v.w);
            }
            __half* dst = g_qkvh + (size_t)(m0 + row)*NQKV + gn;
            *(__half2*)dst       = __halves2half2(__float2half(v.x), __float2half(v.y));
            *(__half2*)(dst + 2) = __halves2half2(__float2half(v.z), __float2half(v.w));
        } else {
            v.x += bias[gn]; v.y += bias[gn+1]; v.z += bias[gn+2]; v.w += bias[gn+3];
            *(float4*)&CoutExt[(size_t)(m0 + row)*CH + gn] = v;
        }
    }
}

// ------------------------- kv = k^T v partials + ksum partials (fp16 inputs) -------------------------
__global__ void __launch_bounds__(256) kv_partial_kernel() {
    const int s  = blockIdx.x;
    const int bh = blockIdx.y;
    const int b = bh >> 4, h = bh & 15;
    const int tid = threadIdx.x;
    const int d  = tid >> 2;
    const int e0 = (tid & 3) << 4;

    __shared__ __align__(16) float ks_[8][64];
    __shared__ __align__(16) float vs_[8][64];

    float acc[16];
    #pragma unroll
    for (int i = 0; i < 16; i++) acc[i] = 0.0f;
    float ksum = 0.0f;

    const __half* kbase = g_qkvh + (size_t)(b*SEQ)*NQKV + CH + h*DH;
    const __half* vbase = kbase + CH;
    int nbase = s * (SEQ / NSPLIT);
    const int r = tid >> 5, c2 = (tid & 31) * 2;
    for (int it = 0; it < 32; ++it, nbase += 8) {
        {
            const size_t go = (size_t)(nbase + r)*NQKV + c2;
            const __half2 kk = *(const __half2*)&kbase[go];
            const __half2 vv = *(const __half2*)&vbase[go];
            ks_[r][c2]   = __half2float(__low2half(kk));
            ks_[r][c2+1] = __half2float(__high2half(kk));
            vs_[r][c2]   = __half2float(__low2half(vv));
            vs_[r][c2+1] = __half2float(__high2half(vv));
        }
        __syncthreads();
        #pragma unroll
        for (int rr = 0; rr < 8; ++rr) {
            const float kd = ks_[rr][d];
            ksum += kd;
            #pragma unroll
            for (int j4 = 0; j4 < 4; ++j4) {
                const float4 vv = *(const float4*)&vs_[rr][e0 + j4*4];
                acc[j4*4+0] += kd*vv.x; acc[j4*4+1] += kd*vv.y;
                acc[j4*4+2] += kd*vv.z; acc[j4*4+3] += kd*vv.w;
            }
        }
        __syncthreads();
    }
    float* outp = g_kv_part + ((size_t)s*BHCNT + bh)*(DH*DH) + d*DH + e0;
    #pragma unroll
    for (int j4 = 0; j4 < 4; ++j4)
        *(float4*)&outp[j4*4] = make_float4(acc[j4*4], acc[j4*4+1], acc[j4*4+2], acc[j4*4+3]);
    if ((tid & 3) == 0)
        g_ksum_part[((size_t)s*BHCNT + bh)*DH + d] = ksum;
}

__global__ void kv_reduce_kernel() {
    const int i = blockIdx.x * 256 + threadIdx.x;
    float s = 0.0f;
    #pragma unroll
    for (int p = 0; p < NSPLIT; ++p) s += g_kv_part[(size_t)p*(BHCNT*DH*DH) + i];
    g_kv[i] = s;
}

// ------------------------- out = (q @ kv) / (q . ksum + eps) -> fp16 (denom fused) -------------------------
__global__ void __launch_bounds__(256) attn_kernel() {
    const int bh = blockIdx.y;
    const int chunk = blockIdx.x;
    const int b = bh >> 4, h = bh & 15;
    const int tid = threadIdx.x;
    const int base = chunk * 64;

    __shared__ __align__(16) float kv_s[64*64];
    __shared__ float q_s[64*65];
    __shared__ float ksum_s[64];
    __shared__ float inv_s[64];

    for (int i = tid; i < DH*DH; i += 256) kv_s[i] = g_kv[(size_t)bh*(DH*DH) + i];
    for (int i = tid; i < 64*64; i += 256) {
        const int r = i >> 6, d = i & 63;
        q_s[r*65 + d] = __half2float(g_qkvh[(size_t)(b*SEQ + base + r)*NQKV + h*DH + d]);
    }
    if (tid < 64) {
        float s = 0.0f;
        #pragma unroll
        for (int p = 0; p < NSPLIT; ++p) s += g_ksum_part[((size_t)p*BHCNT + bh)*DH + tid];
        ksum_s[tid] = s;
    }
    __syncthreads();
    if (tid < 64) {
        float a = 0.0f;
        #pragma unroll 16
        for (int d = 0; d < DH; ++d) a += q_s[tid*65 + d] * ksum_s[d];
        inv_s[tid] = 1.0f / (a + 1e-6f);
    }
    __syncthreads();

    const int rsub = tid >> 4;
    const int e4   = (tid & 15) << 2;
    #pragma unroll
    for (int p = 0; p < 4; ++p) {
        const int row = p*16 + rsub;
        float4 acc = make_float4(0.f, 0.f, 0.f, 0.f);
        #pragma unroll 8
        for (int d = 0; d < DH; ++d) {
            const float qv = q_s[row*65 + d];
            const float4 kvv = *(const float4*)&kv_s[d*DH + e4];
            acc.x += qv*kvv.x; acc.y += qv*kvv.y; acc.z += qv*kvv.z; acc.w += qv*kvv.w;
        }
        const float inv = inv_s[row];
        const size_t off = (size_t)(b*SEQ + base + row)*CH + h*DH + e4;
        *(__half2*)(g_attn_h + off)     = __halves2half2(__float2half(acc.x*inv), __float2half(acc.y*inv));
        *(__half2*)(g_attn_h + off + 2) = __halves2half2(__float2half(acc.z*inv), __float2half(acc.w*inv));
    }
}

// ------------------------- launch -------------------------
extern "C" void kernel_launch(void* const* d_in, const int* in_sizes, int n_in,
                              void* d_out, int out_size) {
    (void)in_sizes; (void)n_in; (void)out_size;
    const float* x     = (const float*)d_in[0];
    const float* w_qkv = (const float*)d_in[1];
    const float* w_out = (const float*)d_in[2];
    const float* b_out = (const float*)d_in[3];
    float* out = (float*)d_out;

    __half *xh, *wqkvh, *wouth;
    cudaGetSymbolAddress((void**)&xh,    g_xh);
    cudaGetSymbolAddress((void**)&wqkvh, g_wqkvh);
    cudaGetSymbolAddress((void**)&wouth, g_wouth);

    cvt_kernel<<<4096, 256>>>(x,     xh,    MROWS*KDIM);
    cvt_kernel<<<2048, 256>>>(w_qkv, wqkvh, NQKV*KDIM);
    cvt_kernel<<<1024, 256>>>(w_out, wouth, CH*KDIM);

    cudaFuncSetAttribute(gemm_f16<0>, cudaFuncAttributeMaxDynamicSharedMemorySize, (int)GEMM_SMEM);
    gemm_f16<0><<<dim3(NQKV/BN, MROWS/BM), 256, GEMM_SMEM>>>(nullptr, nullptr);

    kv_partial_kernel<<<dim3(NSPLIT, BHCNT), 256>>>();
    kv_reduce_kernel<<<(BHCNT*DH*DH)/256, 256>>>();
    attn_kernel<<<dim3(SEQ/64, BHCNT), 256>>>();

    cudaFuncSetAttribute(gemm_f16<1>, cudaFuncAttributeMaxDynamicSharedMemorySize, (int)GEMM_SMEM);
    gemm_f16<1><<<dim3(CH/BN, MROWS/BM), 256, GEMM_SMEM>>>(out, b_out);
}

// round 16
// speedup vs baseline: 6.4488x; 1.6535x over previous
#include <cuda_runtime.h>
#include <cuda_fp16.h>
#include <mma.h>
#include <cstdint>

using namespace nvcuda;

#define BATCH 4
#define SEQ   4096
#define CH    1024
#define NHEAD 16
#define DH    64
#define MROWS (BATCH*SEQ)     /* 16384 */
#define KDIM  CH              /* 1024  */
#define NQKV  (3*CH)          /* 3072  */
#define NSPLIT 16
#define BHCNT (BATCH*NHEAD)   /* 64    */

// GEMM tiling
#define BM 128
#define BN 128
#define BK 32
#define NT (KDIM/BK)            /* 32 K-tiles */
#define STAGES 4
#define LDA 40                  /* half elems; 80 B row stride (16B-aligned) */
#define ARR_BYTES (128*LDA*2)   /* 10240 B per array (A/B)                  */
#define STAGE_BYTES (2*ARR_BYTES)          /* 20480 */
#define GEMM_SMEM (STAGES*STAGE_BYTES)     /* 81920 */

// ------------------------- scratch (device globals; no allocs) -------------------------
__device__ __half g_xh[(size_t)MROWS*KDIM];
__device__ __half g_wqkvh[(size_t)NQKV*KDIM];
__device__ __half g_wouth[(size_t)CH*KDIM];
__device__ __half g_qkvh[(size_t)MROWS*NQKV];          // q,k (feat applied), v — fp16
__device__ float  g_kv_part[(size_t)NSPLIT*BHCNT*DH*DH];
__device__ float  g_ksum_part[(size_t)NSPLIT*BHCNT*DH];
__device__ float  g_kv[(size_t)BHCNT*DH*DH];
__device__ __half g_attn_h[(size_t)MROWS*CH];

// ------------------------- helpers -------------------------
__device__ __forceinline__ uint32_t smem_u32(const void* p) {
    uint32_t a;
    asm("{ .reg .u64 t; cvta.to.shared.u64 t, %1; cvt.u32.u64 %0, t; }" : "=r"(a) : "l"(p));
    return a;
}
__device__ __forceinline__ void cp_async16(uint32_t s, const void* g) {
    asm volatile("cp.async.cg.shared.global [%0], [%1], 16;" :: "r"(s), "l"(g) : "memory");
}
__device__ __forceinline__ void cp_commit() {
    asm volatile("cp.async.commit_group;" ::: "memory");
}
template<int N>
__device__ __forceinline__ void cp_wait() {
    asm volatile("cp.async.wait_group %0;" :: "n"(N) : "memory");
}
__device__ __forceinline__ float featf(float x) {
    const float s = 0.35355339059327373f;       // 64^-0.25
    return (x > 0.0f) ? (x + 1.0f) * s : __expf(x) * s;
}

// ------------------------- fp32 -> fp16 convert -------------------------
__global__ void cvt_kernel(const float* __restrict__ src, __half* __restrict__ dst, int n) {
    int i = blockIdx.x * blockDim.x + threadIdx.x;
    int stride = gridDim.x * blockDim.x;
    for (; i < n; i += stride) dst[i] = __float2half(src[i]);
}

// ------------------------- fp16 GEMM: C[m,n] = sum_k A[m,k]*B[n,k], f32 acc -------------------------
// MODE 0: x @ wqkv^T -> g_qkvh fp16 (feat on q,k cols). MODE 1: attn @ wout^T + bias -> fp32 out.
template<int MODE>
__global__ void __launch_bounds__(256) gemm_f16(float* __restrict__ CoutExt,
                                                const float* __restrict__ bias) {
    const __half* __restrict__ Ah = (MODE == 0) ? g_xh    : g_attn_h;
    const __half* __restrict__ Bh = (MODE == 0) ? g_wqkvh : g_wouth;

    extern __shared__ __align__(16) char smem_raw[];
    const uint32_t sb = smem_u32(smem_raw);

    const int tid = threadIdx.x;
    const int wid = tid >> 5;
    const int wm_ = wid >> 2;    // 0..1 (M dir, 64 rows each)
    const int wn_ = wid & 3;     // 0..3 (N dir, 32 cols each)
    const int m0 = blockIdx.y * BM;
    const int n0 = blockIdx.x * BN;

    const char* gptr[4];
    uint32_t    sptr[4];
    #pragma unroll
    for (int j = 0; j < 4; ++j) {
        const int idx = tid + j * 256;
        const int arr = idx >> 9, r = (idx >> 2) & 127, c16 = idx & 3;
        const __half* base = (arr == 0) ? Ah : Bh;
        const int row = ((arr == 0) ? m0 : n0) + r;
        gptr[j] = (const char*)(base + (size_t)row * KDIM + c16 * 8);
        sptr[j] = sb + arr * ARR_BYTES + r * (LDA * 2) + c16 * 16;
    }

    wmma::fragment<wmma::accumulator,16,16,16,float> acc[4][2];
    #pragma unroll
    for (int i = 0; i < 4; i++)
        #pragma unroll
        for (int j = 0; j < 2; j++) wmma::fill_fragment(acc[i][j], 0.0f);

    #pragma unroll
    for (int s = 0; s < STAGES - 1; ++s) {
        const uint32_t so = (uint32_t)s * STAGE_BYTES;
        #pragma unroll
        for (int j = 0; j < 4; ++j) cp_async16(sptr[j] + so, gptr[j] + (size_t)s * (BK*2));
        cp_commit();
    }

    for (int kt = 0; kt < NT; ++kt) {
        cp_wait<STAGES - 2>();
        __syncthreads();

        const int ns = kt + STAGES - 1;
        if (ns < NT) {
            const uint32_t so = (uint32_t)(ns & (STAGES-1)) * STAGE_BYTES;
            #pragma unroll
            for (int j = 0; j < 4; ++j) cp_async16(sptr[j] + so, gptr[j] + (size_t)ns * (BK*2));
        }
        cp_commit();

        const __half* sA = (const __half*)(smem_raw + (size_t)(kt & (STAGES-1)) * STAGE_BYTES);
        const __half* sB = sA + 128*LDA;
        const __half* pA = sA + wm_*64*LDA;
        const __half* pB = sB + wn_*32*LDA;

        #pragma unroll
        for (int ks = 0; ks < BK; ks += 16) {
            wmma::fragment<wmma::matrix_a,16,16,16,__half,wmma::row_major> a[4];
            wmma::fragment<wmma::matrix_b,16,16,16,__half,wmma::col_major> b[2];
            #pragma unroll
            for (int i = 0; i < 4; i++) wmma::load_matrix_sync(a[i], pA + i*16*LDA + ks, LDA);
            #pragma unroll
            for (int j = 0; j < 2; j++) wmma::load_matrix_sync(b[j], pB + j*16*LDA + ks, LDA);
            #pragma unroll
            for (int i = 0; i < 4; i++)
                #pragma unroll
                for (int j = 0; j < 2; j++) wmma::mma_sync(acc[i][j], a[i], b[j], acc[i][j]);
        }
        __syncthreads();
    }
    cp_wait<0>();
    __syncthreads();

    float* Cs = (float*)smem_raw;   // 128 x 132 f32 = 67584 B
    #pragma unroll
    for (int i = 0; i < 4; i++)
        #pragma unroll
        for (int j = 0; j < 2; j++)
            wmma::store_matrix_sync(Cs + (wm_*64 + i*16)*132 + wn_*32 + j*16,
                                    acc[i][j], 132, wmma::mem_row_major);
    __syncthreads();
    for (int i = tid; i < BM*BN/4; i += 256) {
        const int row = i >> 5;
        const int c4  = (i & 31) << 2;
        float4 v = *(const float4*)&Cs[row*132 + c4];
        const int gn = n0 + c4;
        if (MODE == 0) {
            if (gn < 2*CH) {
                v.x = featf(v.x); v.y = featf(v.y); v.z = featf(v.z); v.w = featf(v.w);
            }
            __half* dst = g_qkvh + (size_t)(m0 + row)*NQKV + gn;
            *(__half2*)dst       = __halves2half2(__float2half(v.x), __float2half(v.y));
            *(__half2*)(dst + 2) = __halves2half2(__float2half(v.z), __float2half(v.w));
        } else {
            v.x += bias[gn]; v.y += bias[gn+1]; v.z += bias[gn+2]; v.w += bias[gn+3];
            *(float4*)&CoutExt[(size_t)(m0 + row)*CH + gn] = v;
        }
    }
}

// ------------------------- kv = k^T v partials + ksum partials (tensor core) -------------------------
// grid (NSPLIT, BHCNT), 128 threads. Per block: C[64x64] = sum over 256 rows of k^T v.
__global__ void __launch_bounds__(128) kv_partial_kernel() {
    const int s  = blockIdx.x;
    const int bh = blockIdx.y;
    const int b = bh >> 4, h = bh & 15;
    const int tid = threadIdx.x;
    const int wid = tid >> 5;

    __shared__ __align__(16) char blob[2*128*72*2];     // 36864 B
    __half* k_s = (__half*)blob;                        // 128 x 72
    __half* v_s = (__half*)(blob + 128*72*2);           // 128 x 72
    __shared__ float ks_red[2][64];

    const __half* kbase = g_qkvh + (size_t)(b*SEQ)*NQKV + CH + h*DH;
    const __half* vbase = kbase + CH;

    wmma::fragment<wmma::accumulator,16,16,16,float> acc[2][2];
    #pragma unroll
    for (int i = 0; i < 2; i++)
        #pragma unroll
        for (int j = 0; j < 2; j++) wmma::fill_fragment(acc[i][j], 0.0f);

    const int wm = wid >> 1, wn = wid & 1;   // 2x2 warp grid, 32x32 per warp
    const int dcol = tid & 63, rhalf = tid >> 6;
    float ksum = 0.0f;

    #pragma unroll
    for (int c = 0; c < 2; ++c) {
        const int nbase = s*256 + c*128;
        {   // each thread copies one 64-half row (8 x uint4)
            const uint4* gk = (const uint4*)(kbase + (size_t)(nbase + tid)*NQKV);
            const uint4* gv = (const uint4*)(vbase + (size_t)(nbase + tid)*NQKV);
            uint4* sk = (uint4*)(k_s + tid*72);
            uint4* sv = (uint4*)(v_s + tid*72);
            #pragma unroll
            for (int q8 = 0; q8 < 8; ++q8) { sk[q8] = gk[q8]; sv[q8] = gv[q8]; }
        }
        __syncthreads();
        {   // ksum partial: thread owns (rhalf, dcol)
            float t = 0.0f;
            #pragma unroll 16
            for (int rr = 0; rr < 64; ++rr)
                t += __half2float(k_s[(rhalf*64 + rr)*72 + dcol]);
            ksum += t;
        }
        #pragma unroll
        for (int k16 = 0; k16 < 8; ++k16) {
            wmma::fragment<wmma::matrix_a,16,16,16,__half,wmma::col_major> af[2];
            wmma::fragment<wmma::matrix_b,16,16,16,__half,wmma::row_major> bf[2];
            #pragma unroll
            for (int i = 0; i < 2; i++)
                wmma::load_matrix_sync(af[i], k_s + k16*16*72 + wm*32 + i*16, 72);
            #pragma unroll
            for (int j = 0; j < 2; j++)
                wmma::load_matrix_sync(bf[j], v_s + k16*16*72 + wn*32 + j*16, 72);
            #pragma unroll
            for (int i = 0; i < 2; i++)
                #pragma unroll
                for (int j = 0; j < 2; j++) wmma::mma_sync(acc[i][j], af[i], bf[j], acc[i][j]);
        }
        __syncthreads();
    }

    ks_red[rhalf][dcol] = ksum;
    float* Cs = (float*)blob;       // 64 x 68 f32 = 17408 B
    #pragma unroll
    for (int i = 0; i < 2; i++)
        #pragma unroll
        for (int j = 0; j < 2; j++)
            wmma::store_matrix_sync(Cs + (wm*32 + i*16)*68 + wn*32 + j*16,
                                    acc[i][j], 68, wmma::mem_row_major);
    __syncthreads();
    float* outp = g_kv_part + ((size_t)s*BHCNT + bh)*(DH*DH);
    for (int i = tid; i < 64*64/4; i += 128) {
        const int row = i >> 4, c4 = (i & 15) << 2;
        *(float4*)&outp[row*64 + c4] = *(const float4*)&Cs[row*68 + c4];
    }
    if (tid < 64)
        g_ksum_part[((size_t)s*BHCNT + bh)*DH + tid] = ks_red[0][tid] + ks_red[1][tid];
}

__global__ void kv_reduce_kernel() {
    const int i = blockIdx.x * 256 + threadIdx.x;
    float s = 0.0f;
    #pragma unroll
    for (int p = 0; p < NSPLIT; ++p) s += g_kv_part[(size_t)p*(BHCNT*DH*DH) + i];
    g_kv[i] = s;
}

// ------------------------- out = (q @ kv) / (q . ksum + eps) -> fp16 (tensor core) -------------------------
// grid (32, BHCNT), 128 threads. Per block: 128 rows. kv split hi/lo fp16, 2-term MMA (exact).
__global__ void __launch_bounds__(128) attn_kernel() {
    const int chunk = blockIdx.x;
    const int bh = blockIdx.y;
    const int b = bh >> 4, h = bh & 15;
    const int tid = threadIdx.x;
    const int wid = tid >> 5;
    const int base = chunk * 128;

    __shared__ __align__(16) char blob[36864];
    __half* q_s   = (__half*)blob;                 // 128 x 72 = 18432 B
    __half* kvh_s = (__half*)(blob + 18432);       // 64 x 72  =  9216 B
    __half* kvl_s = (__half*)(blob + 27648);       // 64 x 72  =  9216 B
    __shared__ float ksum_s[64];
    __shared__ float inv_s[128];

    {   // q tile: one 64-half row per thread
        const uint4* gq = (const uint4*)(g_qkvh + (size_t)(b*SEQ + base + tid)*NQKV + h*DH);
        uint4* sq = (uint4*)(q_s + tid*72);
        #pragma unroll
        for (int q8 = 0; q8 < 8; ++q8) sq[q8] = gq[q8];
    }
    for (int i = tid; i < 64*64; i += 128) {       // kv hi/lo split
        const int r = i >> 6, c = i & 63;
        const float v = g_kv[(size_t)bh*(DH*DH) + i];
        const __half hh = __float2half(v);
        kvh_s[r*72 + c] = hh;
        kvl_s[r*72 + c] = __float2half(v - __half2float(hh));
    }
    if (tid < 64) {
        float s = 0.0f;
        #pragma unroll
        for (int p = 0; p < NSPLIT; ++p) s += g_ksum_part[((size_t)p*BHCNT + bh)*DH + tid];
        ksum_s[tid] = s;
    }
    __syncthreads();
    {   // denom per row (fp32 scalar)
        float a = 0.0f;
        #pragma unroll 16
        for (int d = 0; d < DH; ++d) a += __half2float(q_s[tid*72 + d]) * ksum_s[d];
        inv_s[tid] = 1.0f / (a + 1e-6f);
    }

    // MMA: warp grid 2(M) x 2(N); warp tile 64 x 32
    const int wm = wid >> 1, wn = wid & 1;
    wmma::fragment<wmma::accumulator,16,16,16,float> acc[4][2];
    #pragma unroll
    for (int i = 0; i < 4; i++)
        #pragma unroll
        for (int j = 0; j < 2; j++) wmma::fill_fragment(acc[i][j], 0.0f);
    #pragma unroll
    for (int k16 = 0; k16 < 4; ++k16) {
        wmma::fragment<wmma::matrix_a,16,16,16,__half,wmma::row_major> af[4];
        wmma::fragment<wmma::matrix_b,16,16,16,__half,wmma::row_major> bhf[2], blf[2];
        #pragma unroll
        for (int i = 0; i < 4; i++)
            wmma::load_matrix_sync(af[i], q_s + (wm*64 + i*16)*72 + k16*16, 72);
        #pragma unroll
        for (int j = 0; j < 2; j++) {
            wmma::load_matrix_sync(bhf[j], kvh_s + k16*16*72 + wn*32 + j*16, 72);
            wmma::load_matrix_sync(blf[j], kvl_s + k16*16*72 + wn*32 + j*16, 72);
        }
        #pragma unroll
        for (int i = 0; i < 4; i++)
            #pragma unroll
            for (int j = 0; j < 2; j++) wmma::mma_sync(acc[i][j], af[i], bhf[j], acc[i][j]);
        #pragma unroll
        for (int i = 0; i < 4; i++)
            #pragma unroll
            for (int j = 0; j < 2; j++) wmma::mma_sync(acc[i][j], af[i], blf[j], acc[i][j]);
    }
    __syncthreads();
    float* Cs = (float*)blob;   // 128 x 68 f32 = 34816 B
    #pragma unroll
    for (int i = 0; i < 4; i++)
        #pragma unroll
        for (int j = 0; j < 2; j++)
            wmma::store_matrix_sync(Cs + (wm*64 + i*16)*68 + wn*32 + j*16,
                                    acc[i][j], 68, wmma::mem_row_major);
    __syncthreads();
    for (int i = tid; i < 128*64/4; i += 128) {
        const int row = i >> 4, c4 = (i & 15) << 2;
        const float4 v = *(const float4*)&Cs[row*68 + c4];
        const float inv = inv_s[row];
        __half* dst = g_attn_h + (size_t)(b*SEQ + base + row)*CH + h*DH + c4;
        *(__half2*)dst       = __halves2half2(__float2half(v.x*inv), __float2half(v.y*inv));
        *(__half2*)(dst + 2) = __halves2half2(__float2half(v.z*inv), __float2half(v.w*inv));
    }
}

// ------------------------- launch -------------------------
extern "C" void kernel_launch(void* const* d_in, const int* in_sizes, int n_in,
                              void* d_out, int out_size) {
    (void)in_sizes; (void)n_in; (void)out_size;
    const float* x     = (const float*)d_in[0];
    const float* w_qkv = (const float*)d_in[1];
    const float* w_out = (const float*)d_in[2];
    const float* b_out = (const float*)d_in[3];
    float* out = (float*)d_out;

    __half *xh, *wqkvh, *wouth;
    cudaGetSymbolAddress((void**)&xh,    g_xh);
    cudaGetSymbolAddress((void**)&wqkvh, g_wqkvh);
    cudaGetSymbolAddress((void**)&wouth, g_wouth);

    cvt_kernel<<<4096, 256>>>(x,     xh,    MROWS*KDIM);
    cvt_kernel<<<2048, 256>>>(w_qkv, wqkvh, NQKV*KDIM);
    cvt_kernel<<<1024, 256>>>(w_out, wouth, CH*KDIM);

    cudaFuncSetAttribute(gemm_f16<0>, cudaFuncAttributeMaxDynamicSharedMemorySize, (int)GEMM_SMEM);
    gemm_f16<0><<<dim3(NQKV/BN, MROWS/BM), 256, GEMM_SMEM>>>(nullptr, nullptr);

    kv_partial_kernel<<<dim3(NSPLIT, BHCNT), 128>>>();
    kv_reduce_kernel<<<(BHCNT*DH*DH)/256, 256>>>();
    attn_kernel<<<dim3(32, BHCNT), 128>>>();

    cudaFuncSetAttribute(gemm_f16<1>, cudaFuncAttributeMaxDynamicSharedMemorySize, (int)GEMM_SMEM);
    gemm_f16<1><<<dim3(CH/BN, MROWS/BM), 256, GEMM_SMEM>>>(out, b_out);
}